// round 2
// baseline (speedup 1.0000x reference)
#include <cuda_runtime.h>
#include <math.h>

#define Hh 12
#define Dd 768
#define T1c 512
#define T2c 64
#define Bb 16
#define SPAD 68

static const float PROJ_SCALE = 0.3535533905932738f; // 64^-0.25
#define NEGBIG (-1e9f)

// Scratch (device globals: allowed; no allocation in kernel_launch)
__device__ float g_proj_f[6ull * Bb * T1c * Dd];   // [6][B][H][T1][64]
__device__ float g_proj_i[6ull * Bb * T2c * Dd];   // [6][B][H][T2][64]
__device__ float g_att_v[(size_t)Bb * T1c * Dd];   // [B][T1][768]
__device__ float g_att_l[(size_t)Bb * T2c * Dd];   // [B][T2][768]

// ---------------------------------------------------------------------------
// Tiled SGEMM: C = A[M,768] @ W[768,768] (+bias)(*scale)
// mode 0: projection epilogue -> scatter to [B][H][T][64] layout, apply scale
// mode 1: plain epilogue -> C[m*768+n] = acc + bias[n]
// grid: (N/128, M/128, n_mats); block: 256 threads; 8x8 per thread
// ---------------------------------------------------------------------------
__global__ __launch_bounds__(256) void sgemm_kernel(
    const float* __restrict__ A,
    const float* __restrict__ Wbase,
    const float* __restrict__ biasbase,
    float* __restrict__ Cbase,
    int M, int T, float scale, int mode)
{
    const int z = blockIdx.z;
    const float* W    = Wbase   + (size_t)z * Dd * Dd;
    const float* bias = biasbase + (size_t)z * Dd;
    float*       C    = Cbase   + (size_t)z * M * Dd;

    __shared__ __align__(16) float As[8][128];
    __shared__ __align__(16) float Bs[8][128];

    const int tid = threadIdx.x;
    const int tx = tid & 15;       // column group
    const int ty = tid >> 4;       // row group
    const int m0 = blockIdx.y * 128;
    const int n0 = blockIdx.x * 128;

    float acc[8][8];
#pragma unroll
    for (int i = 0; i < 8; i++)
#pragma unroll
        for (int j = 0; j < 8; j++) acc[i][j] = 0.0f;

    const int arow = tid >> 1;
    const int acol = (tid & 1) * 4;
    const int brow = tid >> 5;
    const int bcol = (tid & 31) * 4;

    for (int k0 = 0; k0 < Dd; k0 += 8) {
        float4 av = *(const float4*)&A[(size_t)(m0 + arow) * Dd + k0 + acol];
        float4 bv = *(const float4*)&W[(size_t)(k0 + brow) * Dd + n0 + bcol];
        __syncthreads();   // previous iteration's reads done
        As[acol + 0][arow] = av.x;
        As[acol + 1][arow] = av.y;
        As[acol + 2][arow] = av.z;
        As[acol + 3][arow] = av.w;
        *(float4*)&Bs[brow][bcol] = bv;
        __syncthreads();
#pragma unroll
        for (int kk = 0; kk < 8; kk++) {
            float a[8], b[8];
            *(float4*)&a[0] = *(const float4*)&As[kk][ty * 8];
            *(float4*)&a[4] = *(const float4*)&As[kk][ty * 8 + 4];
            *(float4*)&b[0] = *(const float4*)&Bs[kk][tx * 8];
            *(float4*)&b[4] = *(const float4*)&Bs[kk][tx * 8 + 4];
#pragma unroll
            for (int i = 0; i < 8; i++)
#pragma unroll
                for (int j = 0; j < 8; j++)
                    acc[i][j] += a[i] * b[j];
        }
    }

    if (mode == 0) {
#pragma unroll
        for (int i = 0; i < 8; i++) {
            const int m = m0 + ty * 8 + i;
            const int b_ = m / T;
            const int t_ = m - b_ * T;
#pragma unroll
            for (int j = 0; j < 8; j++) {
                const int n = n0 + tx * 8 + j;
                const int h = n >> 6;
                const int e = n & 63;
                const float v = scale * (acc[i][j] + bias[n]);
                C[((((size_t)(b_ * Hh + h)) * T + t_) << 6) + e] = v;
            }
        }
    } else {
#pragma unroll
        for (int i = 0; i < 8; i++) {
            const int m = m0 + ty * 8 + i;
#pragma unroll
            for (int j = 0; j < 8; j++) {
                const int n = n0 + tx * 8 + j;
                C[(size_t)m * Dd + n] = acc[i][j] + bias[n];
            }
        }
    }
}

// ---------------------------------------------------------------------------
// Fused flash attention over joint key axis [512 (block1) | 64 (block2)].
// Block1 keys/values come with Q1; the last key tile (block2) uses Q2.
// Mask is per-key (shape [B,576], int32 0/1); masked score replaced by -1e9
// (reference semantics). Output written directly in [B][Tq][768] layout.
// grid: (Tq/64, H, B); block: 256 threads; 4x4 outputs per thread.
// ---------------------------------------------------------------------------
__global__ __launch_bounds__(256) void flash_kernel(
    const float* __restrict__ Q1,
    const float* __restrict__ Q2,
    const float* __restrict__ K1,
    const float* __restrict__ V1,
    const float* __restrict__ K2,
    const float* __restrict__ V2,
    const int* __restrict__ mask,
    float* __restrict__ out,
    int Tq)
{
    extern __shared__ __align__(16) float sm[];
    float* Qs   = sm;                   // [64][SPAD], transposed: Qs[e*SPAD + r]
    float* Ks   = Qs + 64 * SPAD;       // [64][SPAD], transposed: Ks[e*SPAD + j]
    float* Vs   = Ks + 64 * SPAD;       // [64][64]:  Vs[j*64 + e]
    float* Ss   = Vs + 64 * 64;         // [64][SPAD], transposed: Ss[j*SPAD + r]
    float* m_s  = Ss + 64 * SPAD;       // [64]
    float* l_s  = m_s + 64;             // [64]
    float* corr = l_s + 64;             // [64]
    float* mflag = corr + 64;           // [576] 0/1

    const int tid = threadIdx.x;
    const int tx = tid & 15;    // query group (rows)
    const int ty = tid >> 4;    // key/out-dim group (cols)
    const int b = blockIdx.z, h = blockIdx.y, qt = blockIdx.x;

    const float* Q1p = Q1 + (((size_t)(b * Hh + h) * Tq) + qt * 64) * 64;
    const float* Q2p = Q2 + (((size_t)(b * Hh + h) * Tq) + qt * 64) * 64;
    const float* K1p = K1 + ((size_t)(b * Hh + h) * T1c) * 64;
    const float* V1p = V1 + ((size_t)(b * Hh + h) * T1c) * 64;
    const float* K2p = K2 + ((size_t)(b * Hh + h) * T2c) * 64;
    const float* V2p = V2 + ((size_t)(b * Hh + h) * T2c) * 64;

    // Q1 (transposed into smem)
    for (int i = tid; i < 64 * 64; i += 256) {
        const int r = i >> 6, e = i & 63;
        Qs[e * SPAD + r] = Q1p[i];
    }
    // mask flags (mask arrives as int32 0/1 — bool inputs are materialized as i32)
    for (int j = tid; j < T1c + T2c; j += 256)
        mflag[j] = (mask[b * (T1c + T2c) + j] != 0) ? 1.0f : 0.0f;
    if (tid < 64) { m_s[tid] = -1e30f; l_s[tid] = 0.0f; }

    float acc[4][4];
#pragma unroll
    for (int i = 0; i < 4; i++)
#pragma unroll
        for (int j = 0; j < 4; j++) acc[i][j] = 0.0f;

    for (int kt = 0; kt < 9; kt++) {
        const float* Kt;
        const float* Vt;
        int koff;
        if (kt < 8) { Kt = K1p + kt * 64 * 64; Vt = V1p + kt * 64 * 64; koff = kt * 64; }
        else        { Kt = K2p;               Vt = V2p;               koff = T1c; }

        __syncthreads();  // previous tile's consumers done
        if (kt == 8) {
            for (int i = tid; i < 64 * 64; i += 256) {
                const int r = i >> 6, e = i & 63;
                Qs[e * SPAD + r] = Q2p[i];
            }
        }
        for (int i = tid; i < 64 * 64; i += 256) {
            const int j = i >> 6, e = i & 63;
            Ks[e * SPAD + j] = Kt[i];
        }
        for (int i = tid * 4; i < 64 * 64; i += 256 * 4)
            *(float4*)&Vs[i] = *(const float4*)&Vt[i];
        __syncthreads();

        // S = Q^T K  (s[ii][jj]: row tx*4+ii, key ty*4+jj)
        float s[4][4];
#pragma unroll
        for (int i = 0; i < 4; i++)
#pragma unroll
            for (int j = 0; j < 4; j++) s[i][j] = 0.0f;
#pragma unroll 8
        for (int e = 0; e < 64; e++) {
            const float4 q  = *(const float4*)&Qs[e * SPAD + tx * 4];
            const float4 kv = *(const float4*)&Ks[e * SPAD + ty * 4];
            const float qa[4] = {q.x, q.y, q.z, q.w};
            const float ka[4] = {kv.x, kv.y, kv.z, kv.w};
#pragma unroll
            for (int i = 0; i < 4; i++)
#pragma unroll
                for (int j = 0; j < 4; j++)
                    s[i][j] += qa[i] * ka[j];
        }
        // store transposed with mask replacement
#pragma unroll
        for (int jj = 0; jj < 4; jj++) {
            const float mf = mflag[koff + ty * 4 + jj];
            float4 v;
            v.x = (mf != 0.0f) ? NEGBIG : s[0][jj];
            v.y = (mf != 0.0f) ? NEGBIG : s[1][jj];
            v.z = (mf != 0.0f) ? NEGBIG : s[2][jj];
            v.w = (mf != 0.0f) ? NEGBIG : s[3][jj];
            *(float4*)&Ss[(ty * 4 + jj) * SPAD + tx * 4] = v;
        }
        __syncthreads();

        // online softmax per row (64 rows, one thread each)
        if (tid < 64) {
            const float mold = m_s[tid];
            float mx = mold;
            for (int j = 0; j < 64; j++) mx = fmaxf(mx, Ss[j * SPAD + tid]);
            const float c = __expf(mold - mx);
            float sum = 0.0f;
            for (int j = 0; j < 64; j++) {
                const float p = __expf(Ss[j * SPAD + tid] - mx);
                Ss[j * SPAD + tid] = p;
                sum += p;
            }
            l_s[tid] = l_s[tid] * c + sum;
            m_s[tid] = mx;
            corr[tid] = c;
        }
        __syncthreads();

        // rescale accumulators, then O += P @ V
        const float c0 = corr[tx * 4 + 0];
        const float c1 = corr[tx * 4 + 1];
        const float c2 = corr[tx * 4 + 2];
        const float c3 = corr[tx * 4 + 3];
#pragma unroll
        for (int j = 0; j < 4; j++) {
            acc[0][j] *= c0; acc[1][j] *= c1; acc[2][j] *= c2; acc[3][j] *= c3;
        }
#pragma unroll 8
        for (int kk = 0; kk < 64; kk++) {
            const float4 p = *(const float4*)&Ss[kk * SPAD + tx * 4];
            const float4 v = *(const float4*)&Vs[kk * 64 + ty * 4];
            const float pa[4] = {p.x, p.y, p.z, p.w};
            const float va[4] = {v.x, v.y, v.z, v.w};
#pragma unroll
            for (int i = 0; i < 4; i++)
#pragma unroll
                for (int j = 0; j < 4; j++)
                    acc[i][j] += pa[i] * va[j];
        }
    }

    __syncthreads();
#pragma unroll
    for (int ii = 0; ii < 4; ii++) {
        const int r = tx * 4 + ii;
        const float inv = 1.0f / l_s[r];
        const int row = qt * 64 + r;
        float4 o;
        o.x = acc[ii][0] * inv;
        o.y = acc[ii][1] * inv;
        o.z = acc[ii][2] * inv;
        o.w = acc[ii][3] * inv;
        *(float4*)&out[((size_t)b * Tq + row) * Dd + h * 64 + ty * 4] = o;
    }
}

// ---------------------------------------------------------------------------
extern "C" void kernel_launch(void* const* d_in, const int* in_sizes, int n_in,
                              void* d_out, int out_size)
{
    const float* feats = (const float*)d_in[0];
    const float* inps  = (const float*)d_in[1];
    const int*   mask  = (const int*)d_in[2];
    const float* W_f  = (const float*)d_in[3];
    const float* b_f  = (const float*)d_in[4];
    const float* W_i  = (const float*)d_in[5];
    const float* b_i  = (const float*)d_in[6];
    const float* Wu_v = (const float*)d_in[7];
    const float* bu_v = (const float*)d_in[8];
    const float* Wu_l = (const float*)d_in[9];
    const float* bu_l = (const float*)d_in[10];
    float* out = (float*)d_out;

    float *pf, *pi, *av, *al;
    cudaGetSymbolAddress((void**)&pf, g_proj_f);
    cudaGetSymbolAddress((void**)&pi, g_proj_i);
    cudaGetSymbolAddress((void**)&av, g_att_v);
    cudaGetSymbolAddress((void**)&al, g_att_l);

    const size_t SF = (size_t)Bb * T1c * Dd;  // 6291456 (per-slot, feats projections)
    const size_t SI = (size_t)Bb * T2c * Dd;  // 786432  (per-slot, inps projections)

    dim3 blk(256);

    // Projections (scaled by 64^-0.25, scattered to [B][H][T][64])
    // feats slots: 0=k_vv 1=q_vv 2=v_vv 3=q_lv 4=k_vl 5=v_vl
    // inps  slots: 0=k_lv 1=v_lv 2=q_vl 3=q_ll 4=k_ll 5=v_ll
    sgemm_kernel<<<dim3(6, 64, 6), blk>>>(feats, W_f, b_f, pf, Bb * T1c, T1c, PROJ_SCALE, 0);
    sgemm_kernel<<<dim3(6,  8, 6), blk>>>(inps,  W_i, b_i, pi, Bb * T2c, T2c, PROJ_SCALE, 0);

    const int smem = (3 * 64 * SPAD + 64 * 64 + 3 * 64 + (T1c + T2c)) * (int)sizeof(float);
    cudaFuncSetAttribute(flash_kernel, cudaFuncAttributeMaxDynamicSharedMemorySize, smem);

    // Visual stream: Q1=q_vv, Q2=q_lv, K1=k_vv, V1=v_vv, K2=k_lv, V2=v_lv
    flash_kernel<<<dim3(8, Hh, Bb), blk, smem>>>(
        pf + 1 * SF, pf + 3 * SF, pf + 0 * SF, pf + 2 * SF,
        pi + 0 * SI, pi + 1 * SI, mask, av, T1c);

    // Language stream: Q1=q_vl, Q2=q_ll, K1=k_vl, V1=v_vl, K2=k_ll, V2=v_ll
    flash_kernel<<<dim3(1, Hh, Bb), blk, smem>>>(
        pi + 2 * SI, pi + 3 * SI, pf + 4 * SF, pf + 5 * SF,
        pi + 4 * SI, pi + 5 * SI, mask, al, T2c);

    // Output projections -> d_out = [out_v | out_l]
    sgemm_kernel<<<dim3(6, 64, 1), blk>>>(av, Wu_v, bu_v, out,      Bb * T1c, T1c, 1.0f, 1);
    sgemm_kernel<<<dim3(6,  8, 1), blk>>>(al, Wu_l, bu_l, out + SF, Bb * T2c, T2c, 1.0f, 1);
}

// round 5
// speedup vs baseline: 2.0335x; 2.0335x over previous
#include <cuda_runtime.h>
#include <cuda_bf16.h>
#include <cstdint>
#include <math.h>

#define Hh 12
#define Dd 768
#define T1c 512
#define T2c 64
#define Bb 16
#define SPAD 68

static const float PROJ_SCALE = 0.3535533905932738f; // 64^-0.25
#define NEGBIG (-1e9f)

// ======================= PTX helpers (baseline ISA only) ====================
__device__ __forceinline__ uint32_t smem_to_u32(const void* p) {
    uint32_t a;
    asm("{ .reg .u64 t; cvta.to.shared.u64 t, %1; cvt.u32.u64 %0, t; }" : "=r"(a) : "l"(p));
    return a;
}
__device__ __forceinline__ void cp16(uint32_t saddr, const void* g) {
    asm volatile("cp.async.cg.shared.global [%0], [%1], 16;" :: "r"(saddr), "l"(g));
}
__device__ __forceinline__ void ldsm4(uint32_t* r, uint32_t addr) {
    asm volatile("ldmatrix.sync.aligned.m8n8.x4.shared.b16 {%0,%1,%2,%3}, [%4];"
        : "=r"(r[0]), "=r"(r[1]), "=r"(r[2]), "=r"(r[3]) : "r"(addr));
}
__device__ __forceinline__ void mma_bf16(float* c, const uint32_t* a, const uint32_t* b) {
    asm volatile(
        "mma.sync.aligned.m16n8k16.row.col.f32.bf16.bf16.f32 "
        "{%0,%1,%2,%3}, {%4,%5,%6,%7}, {%8,%9}, {%0,%1,%2,%3};"
        : "+f"(c[0]), "+f"(c[1]), "+f"(c[2]), "+f"(c[3])
        : "r"(a[0]), "r"(a[1]), "r"(a[2]), "r"(a[3]), "r"(b[0]), "r"(b[1]));
}

// ======================= scratch (device globals) ===========================
__device__ float g_proj_f[6ull * Bb * T1c * Dd];   // [6][B][H][T1][64]
__device__ float g_proj_i[6ull * Bb * T2c * Dd];   // [6][B][H][T2][64]
__device__ float g_att_v[(size_t)Bb * T1c * Dd];   // [B][T1][768]
__device__ float g_att_l[(size_t)Bb * T2c * Dd];   // [B][T2][768]

__device__ __nv_bfloat16 g_fh[(size_t)Bb * T1c * Dd], g_fl[(size_t)Bb * T1c * Dd];
__device__ __nv_bfloat16 g_ih[(size_t)Bb * T2c * Dd], g_il[(size_t)Bb * T2c * Dd];
__device__ __nv_bfloat16 g_wfh[6ull * Dd * Dd], g_wfl[6ull * Dd * Dd];
__device__ __nv_bfloat16 g_wih[6ull * Dd * Dd], g_wil[6ull * Dd * Dd];
__device__ __nv_bfloat16 g_wuvh[(size_t)Dd * Dd], g_wuvl[(size_t)Dd * Dd];
__device__ __nv_bfloat16 g_wulh[(size_t)Dd * Dd], g_wull[(size_t)Dd * Dd];
__device__ __nv_bfloat16 g_avh[(size_t)Bb * T1c * Dd], g_avl[(size_t)Bb * T1c * Dd];
__device__ __nv_bfloat16 g_alh[(size_t)Bb * T2c * Dd], g_all[(size_t)Bb * T2c * Dd];

// ======================= conversion kernels =================================
__global__ __launch_bounds__(256) void conv_split(
    const float* __restrict__ x, __nv_bfloat16* __restrict__ hi,
    __nv_bfloat16* __restrict__ lo, int n)
{
    int i = blockIdx.x * 256 + threadIdx.x;
    if (i < n) {
        float v = x[i];
        __nv_bfloat16 h = __float2bfloat16(v);
        hi[i] = h;
        lo[i] = __float2bfloat16(v - __bfloat162float(h));
    }
}

// W [z][K=768][N=768] -> out[z][N][K] hi/lo (K-major B operand)
__global__ __launch_bounds__(256) void conv_wsplit(
    const float* __restrict__ W, __nv_bfloat16* __restrict__ bh,
    __nv_bfloat16* __restrict__ bl)
{
    __shared__ float t[32][33];
    const float* Wz = W + (size_t)blockIdx.z * Dd * Dd;
    const int k0 = blockIdx.y * 32, n0 = blockIdx.x * 32;
    const int tx = threadIdx.x & 31, ty = threadIdx.x >> 5; // 32 x 8
#pragma unroll
    for (int j = 0; j < 32; j += 8)
        t[ty + j][tx] = Wz[(size_t)(k0 + ty + j) * Dd + n0 + tx];
    __syncthreads();
#pragma unroll
    for (int j = 0; j < 32; j += 8) {
        float v = t[tx][ty + j];  // = W[k0+tx][n0+ty+j]
        size_t o = (size_t)blockIdx.z * Dd * Dd + (size_t)(n0 + ty + j) * Dd + k0 + tx;
        __nv_bfloat16 h = __float2bfloat16(v);
        bh[o] = h;
        bl[o] = __float2bfloat16(v - __bfloat162float(h));
    }
}

// ======================= mma.sync split-bf16 GEMM ===========================
// C = A[M,768] @ W[768,768] (+bias)(*scale); A/W as bf16 hi+lo.
// B operand K-major [z][N][K]. Tile 128x128, BK=32, double-buffered cp.async.
// 8 warps: warp tile 64x32 (wm = wid&1, wn = wid>>1), m16n8k16 4x4 per warp.
// Split product: Ah*Bh + Ah*Bl + Al*Bh  (3 MMAs per fragment pair).
// B fragment: SMEM [n][k] row-major IS col-major kxn -> ldmatrix WITHOUT trans.
#define ROWB 80                 // 32 bf16 + 8 pad = 40 elems = 80 bytes/row
#define TILE_B (128 * ROWB)     // 10240
#define STAGE_B (4 * TILE_B)    // 40960: [Ah | Al | Bh | Bl]
#define GEMM_SMEM (2 * STAGE_B) // 81920

__global__ __launch_bounds__(256) void gemm_mma(
    const __nv_bfloat16* __restrict__ Ah, const __nv_bfloat16* __restrict__ Al,
    const __nv_bfloat16* __restrict__ Bh, const __nv_bfloat16* __restrict__ Bl,
    const float* __restrict__ biasbase, float* __restrict__ Cbase,
    int M, int T, float scale, int mode)
{
    extern __shared__ __align__(16) char smem[];
    const uint32_t sb = smem_to_u32(smem);
    const int tid = threadIdx.x, lane = tid & 31, wid = tid >> 5;
    const int wm = wid & 1, wn = wid >> 1;
    const int z = blockIdx.z;
    const int m0 = blockIdx.y * 128, n0 = blockIdx.x * 128;

    const __nv_bfloat16* srcs[4];
    srcs[0] = Ah; srcs[1] = Al;
    srcs[2] = Bh + (size_t)z * Dd * Dd; srcs[3] = Bl + (size_t)z * Dd * Dd;

    float acc[4][4][4];
#pragma unroll
    for (int a = 0; a < 4; a++)
#pragma unroll
        for (int b = 0; b < 4; b++)
#pragma unroll
            for (int c = 0; c < 4; c++) acc[a][b][c] = 0.0f;

#define LOAD_STAGE(kc, s) do {                                                \
    _Pragma("unroll")                                                         \
    for (int t_ = 0; t_ < 4; t_++) {                                          \
        const __nv_bfloat16* src_ = srcs[t_];                                 \
        const int rowbase_ = (t_ < 2) ? m0 : n0;                              \
        _Pragma("unroll")                                                     \
        for (int u_ = 0; u_ < 2; u_++) {                                      \
            const int idx_ = tid * 2 + u_;                                    \
            const int row_ = idx_ >> 2, cc_ = idx_ & 3;                       \
            cp16(sb + (s) * STAGE_B + t_ * TILE_B + row_ * ROWB + cc_ * 16,   \
                 src_ + (size_t)(rowbase_ + row_) * Dd + (kc) * 32 + cc_ * 8);\
        }                                                                     \
    }                                                                         \
    asm volatile("cp.async.commit_group;" ::: "memory");                      \
} while (0)

    LOAD_STAGE(0, 0);

    for (int i = 0; i < 24; i++) {
        const int s = i & 1;
        if (i + 1 < 24) {
            LOAD_STAGE(i + 1, s ^ 1);
            asm volatile("cp.async.wait_group 1;" ::: "memory");
        } else {
            asm volatile("cp.async.wait_group 0;" ::: "memory");
        }
        __syncthreads();

        const uint32_t st = sb + s * STAGE_B;
#pragma unroll
        for (int ks = 0; ks < 2; ks++) {
            const int kb = ks * 32;   // byte offset along K within the row
            uint32_t bh[4][2], bl[4][2];
#pragma unroll
            for (int p = 0; p < 2; p++) {
                uint32_t r[4];
                uint32_t ab = st + 2 * TILE_B +
                              (wn * 32 + p * 16 + (lane & 15)) * ROWB +
                              ((lane >> 4) * 16) + kb;
                ldsm4(r, ab);                      // non-trans: [n][k] == col-major kxn
                bh[p * 2][0] = r[0]; bh[p * 2 + 1][0] = r[1];
                bh[p * 2][1] = r[2]; bh[p * 2 + 1][1] = r[3];
                ldsm4(r, ab + TILE_B);
                bl[p * 2][0] = r[0]; bl[p * 2 + 1][0] = r[1];
                bl[p * 2][1] = r[2]; bl[p * 2 + 1][1] = r[3];
            }
            uint32_t a[4][4];
#pragma unroll
            for (int mt = 0; mt < 4; mt++)
                ldsm4(a[mt], st + (wm * 64 + mt * 16 + (lane & 15)) * ROWB +
                             ((lane >> 4) * 16) + kb);
#pragma unroll
            for (int mt = 0; mt < 4; mt++)
#pragma unroll
                for (int nt = 0; nt < 4; nt++) {
                    mma_bf16(acc[mt][nt], a[mt], bh[nt]);
                    mma_bf16(acc[mt][nt], a[mt], bl[nt]);
                }
#pragma unroll
            for (int mt = 0; mt < 4; mt++)
                ldsm4(a[mt], st + TILE_B + (wm * 64 + mt * 16 + (lane & 15)) * ROWB +
                             ((lane >> 4) * 16) + kb);
#pragma unroll
            for (int mt = 0; mt < 4; mt++)
#pragma unroll
                for (int nt = 0; nt < 4; nt++)
                    mma_bf16(acc[mt][nt], a[mt], bh[nt]);
        }
        __syncthreads();
    }

    // epilogue: fragment -> global (float2 stores)
    const float* bias = biasbase + (size_t)z * Dd;
    float* C = Cbase + (size_t)z * M * Dd;
#pragma unroll
    for (int mt = 0; mt < 4; mt++)
#pragma unroll
        for (int nt = 0; nt < 4; nt++) {
            const int n = n0 + wn * 32 + nt * 8 + (lane & 3) * 2;
            const float2 bv = *(const float2*)&bias[n];
#pragma unroll
            for (int hf = 0; hf < 2; hf++) {
                const int m = m0 + wm * 64 + mt * 16 + (lane >> 2) + hf * 8;
                float2 v;
                v.x = scale * (acc[mt][nt][hf * 2 + 0] + bv.x);
                v.y = scale * (acc[mt][nt][hf * 2 + 1] + bv.y);
                if (mode == 0) {
                    const int b_ = m / T, t_ = m - b_ * T;
                    const int h = n >> 6, e = n & 63;
                    *(float2*)&C[((((size_t)(b_ * Hh + h)) * T + t_) << 6) + e] = v;
                } else {
                    *(float2*)&C[(size_t)m * Dd + n] = v;
                }
            }
        }
}

// ======================= flash attention (unchanged, passing) ===============
__global__ __launch_bounds__(256) void flash_kernel(
    const float* __restrict__ Q1,
    const float* __restrict__ Q2,
    const float* __restrict__ K1,
    const float* __restrict__ V1,
    const float* __restrict__ K2,
    const float* __restrict__ V2,
    const int* __restrict__ mask,
    float* __restrict__ out,
    int Tq)
{
    extern __shared__ __align__(16) float sm[];
    float* Qs   = sm;
    float* Ks   = Qs + 64 * SPAD;
    float* Vs   = Ks + 64 * SPAD;
    float* Ss   = Vs + 64 * 64;
    float* m_s  = Ss + 64 * SPAD;
    float* l_s  = m_s + 64;
    float* corr = l_s + 64;
    float* mflag = corr + 64;

    const int tid = threadIdx.x;
    const int tx = tid & 15;
    const int ty = tid >> 4;
    const int b = blockIdx.z, h = blockIdx.y, qt = blockIdx.x;

    const float* Q1p = Q1 + (((size_t)(b * Hh + h) * Tq) + qt * 64) * 64;
    const float* Q2p = Q2 + (((size_t)(b * Hh + h) * Tq) + qt * 64) * 64;
    const float* K1p = K1 + ((size_t)(b * Hh + h) * T1c) * 64;
    const float* V1p = V1 + ((size_t)(b * Hh + h) * T1c) * 64;
    const float* K2p = K2 + ((size_t)(b * Hh + h) * T2c) * 64;
    const float* V2p = V2 + ((size_t)(b * Hh + h) * T2c) * 64;

    for (int i = tid; i < 64 * 64; i += 256) {
        const int r = i >> 6, e = i & 63;
        Qs[e * SPAD + r] = Q1p[i];
    }
    for (int j = tid; j < T1c + T2c; j += 256)
        mflag[j] = (mask[b * (T1c + T2c) + j] != 0) ? 1.0f : 0.0f;
    if (tid < 64) { m_s[tid] = -1e30f; l_s[tid] = 0.0f; }

    float acc[4][4];
#pragma unroll
    for (int i = 0; i < 4; i++)
#pragma unroll
        for (int j = 0; j < 4; j++) acc[i][j] = 0.0f;

    for (int kt = 0; kt < 9; kt++) {
        const float* Kt;
        const float* Vt;
        int koff;
        if (kt < 8) { Kt = K1p + kt * 64 * 64; Vt = V1p + kt * 64 * 64; koff = kt * 64; }
        else        { Kt = K2p;               Vt = V2p;               koff = T1c; }

        __syncthreads();
        if (kt == 8) {
            for (int i = tid; i < 64 * 64; i += 256) {
                const int r = i >> 6, e = i & 63;
                Qs[e * SPAD + r] = Q2p[i];
            }
        }
        for (int i = tid; i < 64 * 64; i += 256) {
            const int j = i >> 6, e = i & 63;
            Ks[e * SPAD + j] = Kt[i];
        }
        for (int i = tid * 4; i < 64 * 64; i += 256 * 4)
            *(float4*)&Vs[i] = *(const float4*)&Vt[i];
        __syncthreads();

        float s[4][4];
#pragma unroll
        for (int i = 0; i < 4; i++)
#pragma unroll
            for (int j = 0; j < 4; j++) s[i][j] = 0.0f;
#pragma unroll 8
        for (int e = 0; e < 64; e++) {
            const float4 q  = *(const float4*)&Qs[e * SPAD + tx * 4];
            const float4 kv = *(const float4*)&Ks[e * SPAD + ty * 4];
            const float qa[4] = {q.x, q.y, q.z, q.w};
            const float ka[4] = {kv.x, kv.y, kv.z, kv.w};
#pragma unroll
            for (int i = 0; i < 4; i++)
#pragma unroll
                for (int j = 0; j < 4; j++)
                    s[i][j] += qa[i] * ka[j];
        }
#pragma unroll
        for (int jj = 0; jj < 4; jj++) {
            const float mf = mflag[koff + ty * 4 + jj];
            float4 v;
            v.x = (mf != 0.0f) ? NEGBIG : s[0][jj];
            v.y = (mf != 0.0f) ? NEGBIG : s[1][jj];
            v.z = (mf != 0.0f) ? NEGBIG : s[2][jj];
            v.w = (mf != 0.0f) ? NEGBIG : s[3][jj];
            *(float4*)&Ss[(ty * 4 + jj) * SPAD + tx * 4] = v;
        }
        __syncthreads();

        if (tid < 64) {
            const float mold = m_s[tid];
            float mx = mold;
            for (int j = 0; j < 64; j++) mx = fmaxf(mx, Ss[j * SPAD + tid]);
            const float c = __expf(mold - mx);
            float sum = 0.0f;
            for (int j = 0; j < 64; j++) {
                const float p = __expf(Ss[j * SPAD + tid] - mx);
                Ss[j * SPAD + tid] = p;
                sum += p;
            }
            l_s[tid] = l_s[tid] * c + sum;
            m_s[tid] = mx;
            corr[tid] = c;
        }
        __syncthreads();

        const float c0 = corr[tx * 4 + 0];
        const float c1 = corr[tx * 4 + 1];
        const float c2 = corr[tx * 4 + 2];
        const float c3 = corr[tx * 4 + 3];
#pragma unroll
        for (int j = 0; j < 4; j++) {
            acc[0][j] *= c0; acc[1][j] *= c1; acc[2][j] *= c2; acc[3][j] *= c3;
        }
#pragma unroll 8
        for (int kk = 0; kk < 64; kk++) {
            const float4 p = *(const float4*)&Ss[kk * SPAD + tx * 4];
            const float4 v = *(const float4*)&Vs[kk * 64 + ty * 4];
            const float pa[4] = {p.x, p.y, p.z, p.w};
            const float va[4] = {v.x, v.y, v.z, v.w};
#pragma unroll
            for (int i = 0; i < 4; i++)
#pragma unroll
                for (int j = 0; j < 4; j++)
                    acc[i][j] += pa[i] * va[j];
        }
    }

    __syncthreads();
#pragma unroll
    for (int ii = 0; ii < 4; ii++) {
        const int r = tx * 4 + ii;
        const float inv = 1.0f / l_s[r];
        const int row = qt * 64 + r;
        float4 o;
        o.x = acc[ii][0] * inv;
        o.y = acc[ii][1] * inv;
        o.z = acc[ii][2] * inv;
        o.w = acc[ii][3] * inv;
        *(float4*)&out[((size_t)b * Tq + row) * Dd + h * 64 + ty * 4] = o;
    }
}

// ======================= launch =============================================
extern "C" void kernel_launch(void* const* d_in, const int* in_sizes, int n_in,
                              void* d_out, int out_size)
{
    const float* feats = (const float*)d_in[0];
    const float* inps  = (const float*)d_in[1];
    const int*   mask  = (const int*)d_in[2];
    const float* W_f  = (const float*)d_in[3];
    const float* b_f  = (const float*)d_in[4];
    const float* W_i  = (const float*)d_in[5];
    const float* b_i  = (const float*)d_in[6];
    const float* Wu_v = (const float*)d_in[7];
    const float* bu_v = (const float*)d_in[8];
    const float* Wu_l = (const float*)d_in[9];
    const float* bu_l = (const float*)d_in[10];
    float* out = (float*)d_out;

    float *pf, *pi, *av, *al;
    cudaGetSymbolAddress((void**)&pf, g_proj_f);
    cudaGetSymbolAddress((void**)&pi, g_proj_i);
    cudaGetSymbolAddress((void**)&av, g_att_v);
    cudaGetSymbolAddress((void**)&al, g_att_l);
    __nv_bfloat16 *fh, *fl, *ih, *il, *wfh, *wfl, *wih, *wil;
    __nv_bfloat16 *wuvh, *wuvl, *wulh, *wull, *avh, *avl, *alh, *all_;
    cudaGetSymbolAddress((void**)&fh, g_fh);   cudaGetSymbolAddress((void**)&fl, g_fl);
    cudaGetSymbolAddress((void**)&ih, g_ih);   cudaGetSymbolAddress((void**)&il, g_il);
    cudaGetSymbolAddress((void**)&wfh, g_wfh); cudaGetSymbolAddress((void**)&wfl, g_wfl);
    cudaGetSymbolAddress((void**)&wih, g_wih); cudaGetSymbolAddress((void**)&wil, g_wil);
    cudaGetSymbolAddress((void**)&wuvh, g_wuvh); cudaGetSymbolAddress((void**)&wuvl, g_wuvl);
    cudaGetSymbolAddress((void**)&wulh, g_wulh); cudaGetSymbolAddress((void**)&wull, g_wull);
    cudaGetSymbolAddress((void**)&avh, g_avh); cudaGetSymbolAddress((void**)&avl, g_avl);
    cudaGetSymbolAddress((void**)&alh, g_alh); cudaGetSymbolAddress((void**)&all_, g_all);

    const size_t SF = (size_t)Bb * T1c * Dd;  // 6291456
    const size_t SI = (size_t)Bb * T2c * Dd;  // 786432
    const int NF = (int)SF, NI = (int)SI;

    cudaFuncSetAttribute(gemm_mma, cudaFuncAttributeMaxDynamicSharedMemorySize, GEMM_SMEM);
    const int fsm = (3 * 64 * SPAD + 64 * 64 + 3 * 64 + (T1c + T2c)) * (int)sizeof(float);
    cudaFuncSetAttribute(flash_kernel, cudaFuncAttributeMaxDynamicSharedMemorySize, fsm);

    // 1) fp32 -> bf16 hi/lo conversions
    conv_split<<<(NF + 255) / 256, 256>>>(feats, fh, fl, NF);
    conv_split<<<(NI + 255) / 256, 256>>>(inps, ih, il, NI);
    conv_wsplit<<<dim3(24, 24, 6), 256>>>(W_f, wfh, wfl);
    conv_wsplit<<<dim3(24, 24, 6), 256>>>(W_i, wih, wil);
    conv_wsplit<<<dim3(24, 24, 1), 256>>>(Wu_v, wuvh, wuvl);
    conv_wsplit<<<dim3(24, 24, 1), 256>>>(Wu_l, wulh, wull);

    // 2) projection GEMMs (tensor cores, split-bf16), scatter to [B][H][T][64]
    gemm_mma<<<dim3(6, 64, 6), 256, GEMM_SMEM>>>(fh, fl, wfh, wfl, b_f, pf,
                                                 Bb * T1c, T1c, PROJ_SCALE, 0);
    gemm_mma<<<dim3(6, 8, 6), 256, GEMM_SMEM>>>(ih, il, wih, wil, b_i, pi,
                                                Bb * T2c, T2c, PROJ_SCALE, 0);

    // 3) attention
    flash_kernel<<<dim3(8, Hh, Bb), 256, fsm>>>(
        pf + 1 * SF, pf + 3 * SF, pf + 0 * SF, pf + 2 * SF,
        pi + 0 * SI, pi + 1 * SI, mask, av, T1c);
    flash_kernel<<<dim3(1, Hh, Bb), 256, fsm>>>(
        pi + 2 * SI, pi + 3 * SI, pf + 4 * SF, pf + 5 * SF,
        pi + 4 * SI, pi + 5 * SI, mask, al, T2c);

    // 4) output projections
    conv_split<<<(NF + 255) / 256, 256>>>(av, avh, avl, NF);
    conv_split<<<(NI + 255) / 256, 256>>>(al, alh, all_, NI);
    gemm_mma<<<dim3(6, 64, 1), 256, GEMM_SMEM>>>(avh, avl, wuvh, wuvl, bu_v, out,
                                                 Bb * T1c, T1c, 1.0f, 1);
    gemm_mma<<<dim3(6, 8, 1), 256, GEMM_SMEM>>>(alh, all_, wulh, wull, bu_l, out + SF,
                                                Bb * T2c, T2c, 1.0f, 1);
}

// round 6
// speedup vs baseline: 2.0369x; 1.0017x over previous
#include <cuda_runtime.h>
#include <cuda_bf16.h>
#include <cstdint>
#include <math.h>

#define Hh 12
#define Dd 768
#define T1c 512
#define T2c 64
#define Bb 16
#define SPAD 68

static const float PROJ_SCALE = 0.3535533905932738f; // 64^-0.25
#define NEGBIG (-1e9f)

// ======================= PTX helpers (baseline ISA only) ====================
__device__ __forceinline__ uint32_t smem_to_u32(const void* p) {
    uint32_t a;
    asm("{ .reg .u64 t; cvta.to.shared.u64 t, %1; cvt.u32.u64 %0, t; }" : "=r"(a) : "l"(p));
    return a;
}
__device__ __forceinline__ void cp16(uint32_t saddr, const void* g) {
    asm volatile("cp.async.cg.shared.global [%0], [%1], 16;" :: "r"(saddr), "l"(g));
}
__device__ __forceinline__ void ldsm4(uint32_t* r, uint32_t addr) {
    asm volatile("ldmatrix.sync.aligned.m8n8.x4.shared.b16 {%0,%1,%2,%3}, [%4];"
        : "=r"(r[0]), "=r"(r[1]), "=r"(r[2]), "=r"(r[3]) : "r"(addr));
}
__device__ __forceinline__ void mma_bf16(float* c, const uint32_t* a, const uint32_t* b) {
    asm volatile(
        "mma.sync.aligned.m16n8k16.row.col.f32.bf16.bf16.f32 "
        "{%0,%1,%2,%3}, {%4,%5,%6,%7}, {%8,%9}, {%0,%1,%2,%3};"
        : "+f"(c[0]), "+f"(c[1]), "+f"(c[2]), "+f"(c[3])
        : "r"(a[0]), "r"(a[1]), "r"(a[2]), "r"(a[3]), "r"(b[0]), "r"(b[1]));
}

// ======================= scratch (device globals) ===========================
__device__ float g_proj_f[6ull * Bb * T1c * Dd];   // [6][B][H][T1][64]
__device__ float g_proj_i[6ull * Bb * T2c * Dd];   // [6][B][H][T2][64]
__device__ float g_att_v[(size_t)Bb * T1c * Dd];   // [B][T1][768]
__device__ float g_att_l[(size_t)Bb * T2c * Dd];   // [B][T2][768]

__device__ __nv_bfloat16 g_fh[(size_t)Bb * T1c * Dd], g_fl[(size_t)Bb * T1c * Dd];
__device__ __nv_bfloat16 g_ih[(size_t)Bb * T2c * Dd], g_il[(size_t)Bb * T2c * Dd];
__device__ __nv_bfloat16 g_wfh[6ull * Dd * Dd], g_wfl[6ull * Dd * Dd];
__device__ __nv_bfloat16 g_wih[6ull * Dd * Dd], g_wil[6ull * Dd * Dd];
__device__ __nv_bfloat16 g_wuvh[(size_t)Dd * Dd], g_wuvl[(size_t)Dd * Dd];
__device__ __nv_bfloat16 g_wulh[(size_t)Dd * Dd], g_wull[(size_t)Dd * Dd];
__device__ __nv_bfloat16 g_avh[(size_t)Bb * T1c * Dd], g_avl[(size_t)Bb * T1c * Dd];
__device__ __nv_bfloat16 g_alh[(size_t)Bb * T2c * Dd], g_all[(size_t)Bb * T2c * Dd];

// ======================= conversion kernels =================================
__global__ __launch_bounds__(256) void conv_split(
    const float* __restrict__ x, __nv_bfloat16* __restrict__ hi,
    __nv_bfloat16* __restrict__ lo, int n)
{
    int i = blockIdx.x * 256 + threadIdx.x;
    if (i < n) {
        float v = x[i];
        __nv_bfloat16 h = __float2bfloat16(v);
        hi[i] = h;
        lo[i] = __float2bfloat16(v - __bfloat162float(h));
    }
}

// W [z][K=768][N=768] -> out[z][N][K] hi/lo (K-major B operand)
__global__ __launch_bounds__(256) void conv_wsplit(
    const float* __restrict__ W, __nv_bfloat16* __restrict__ bh,
    __nv_bfloat16* __restrict__ bl)
{
    __shared__ float t[32][33];
    const float* Wz = W + (size_t)blockIdx.z * Dd * Dd;
    const int k0 = blockIdx.y * 32, n0 = blockIdx.x * 32;
    const int tx = threadIdx.x & 31, ty = threadIdx.x >> 5; // 32 x 8
#pragma unroll
    for (int j = 0; j < 32; j += 8)
        t[ty + j][tx] = Wz[(size_t)(k0 + ty + j) * Dd + n0 + tx];
    __syncthreads();
#pragma unroll
    for (int j = 0; j < 32; j += 8) {
        float v = t[tx][ty + j];  // = W[k0+tx][n0+ty+j]
        size_t o = (size_t)blockIdx.z * Dd * Dd + (size_t)(n0 + ty + j) * Dd + k0 + tx;
        __nv_bfloat16 h = __float2bfloat16(v);
        bh[o] = h;
        bl[o] = __float2bfloat16(v - __bfloat162float(h));
    }
}

// ======================= mma.sync split-bf16 GEMM ===========================
// C = A[M,768] @ W[768,768] (+bias)(*scale); A/W as bf16 hi+lo.
// B operand K-major [z][N][K]. Tile 128x128, BK=32, double-buffered cp.async.
// 8 warps: warp tile 64x32 (wm = wid&1, wn = wid>>1), m16n8k16 4x4 per warp.
// Split product: Ah*Bh + Ah*Bl + Al*Bh  (3 MMAs per fragment pair).
// B fragment: SMEM [n][k] row-major IS col-major kxn -> ldmatrix WITHOUT trans.
#define ROWB 80                 // 32 bf16 + 8 pad = 40 elems = 80 bytes/row
#define TILE_B (128 * ROWB)     // 10240
#define STAGE_B (4 * TILE_B)    // 40960: [Ah | Al | Bh | Bl]
#define GEMM_SMEM (2 * STAGE_B) // 81920

__global__ __launch_bounds__(256) void gemm_mma(
    const __nv_bfloat16* __restrict__ Ah, const __nv_bfloat16* __restrict__ Al,
    const __nv_bfloat16* __restrict__ Bh, const __nv_bfloat16* __restrict__ Bl,
    const float* __restrict__ biasbase, float* __restrict__ Cbase,
    int M, int T, float scale, int mode)
{
    extern __shared__ __align__(16) char smem[];
    const uint32_t sb = smem_to_u32(smem);
    const int tid = threadIdx.x, lane = tid & 31, wid = tid >> 5;
    const int wm = wid & 1, wn = wid >> 1;
    const int z = blockIdx.z;
    const int m0 = blockIdx.y * 128, n0 = blockIdx.x * 128;

    const __nv_bfloat16* srcs[4];
    srcs[0] = Ah; srcs[1] = Al;
    srcs[2] = Bh + (size_t)z * Dd * Dd; srcs[3] = Bl + (size_t)z * Dd * Dd;

    float acc[4][4][4];
#pragma unroll
    for (int a = 0; a < 4; a++)
#pragma unroll
        for (int b = 0; b < 4; b++)
#pragma unroll
            for (int c = 0; c < 4; c++) acc[a][b][c] = 0.0f;

#define LOAD_STAGE(kc, s) do {                                                \
    _Pragma("unroll")                                                         \
    for (int t_ = 0; t_ < 4; t_++) {                                          \
        const __nv_bfloat16* src_ = srcs[t_];                                 \
        const int rowbase_ = (t_ < 2) ? m0 : n0;                              \
        _Pragma("unroll")                                                     \
        for (int u_ = 0; u_ < 2; u_++) {                                      \
            const int idx_ = tid * 2 + u_;                                    \
            const int row_ = idx_ >> 2, cc_ = idx_ & 3;                       \
            cp16(sb + (s) * STAGE_B + t_ * TILE_B + row_ * ROWB + cc_ * 16,   \
                 src_ + (size_t)(rowbase_ + row_) * Dd + (kc) * 32 + cc_ * 8);\
        }                                                                     \
    }                                                                         \
    asm volatile("cp.async.commit_group;" ::: "memory");                      \
} while (0)

    LOAD_STAGE(0, 0);

    for (int i = 0; i < 24; i++) {
        const int s = i & 1;
        if (i + 1 < 24) {
            LOAD_STAGE(i + 1, s ^ 1);
            asm volatile("cp.async.wait_group 1;" ::: "memory");
        } else {
            asm volatile("cp.async.wait_group 0;" ::: "memory");
        }
        __syncthreads();

        const uint32_t st = sb + s * STAGE_B;
#pragma unroll
        for (int ks = 0; ks < 2; ks++) {
            const int kb = ks * 32;   // byte offset along K within the row
            uint32_t bh[4][2], bl[4][2];
#pragma unroll
            for (int p = 0; p < 2; p++) {
                uint32_t r[4];
                uint32_t ab = st + 2 * TILE_B +
                              (wn * 32 + p * 16 + (lane & 15)) * ROWB +
                              ((lane >> 4) * 16) + kb;
                ldsm4(r, ab);                      // non-trans: [n][k] == col-major kxn
                bh[p * 2][0] = r[0]; bh[p * 2 + 1][0] = r[1];
                bh[p * 2][1] = r[2]; bh[p * 2 + 1][1] = r[3];
                ldsm4(r, ab + TILE_B);
                bl[p * 2][0] = r[0]; bl[p * 2 + 1][0] = r[1];
                bl[p * 2][1] = r[2]; bl[p * 2 + 1][1] = r[3];
            }
            uint32_t a[4][4];
#pragma unroll
            for (int mt = 0; mt < 4; mt++)
                ldsm4(a[mt], st + (wm * 64 + mt * 16 + (lane & 15)) * ROWB +
                             ((lane >> 4) * 16) + kb);
#pragma unroll
            for (int mt = 0; mt < 4; mt++)
#pragma unroll
                for (int nt = 0; nt < 4; nt++) {
                    mma_bf16(acc[mt][nt], a[mt], bh[nt]);
                    mma_bf16(acc[mt][nt], a[mt], bl[nt]);
                }
#pragma unroll
            for (int mt = 0; mt < 4; mt++)
                ldsm4(a[mt], st + TILE_B + (wm * 64 + mt * 16 + (lane & 15)) * ROWB +
                             ((lane >> 4) * 16) + kb);
#pragma unroll
            for (int mt = 0; mt < 4; mt++)
#pragma unroll
                for (int nt = 0; nt < 4; nt++)
                    mma_bf16(acc[mt][nt], a[mt], bh[nt]);
        }
        __syncthreads();
    }

    // epilogue: fragment -> global (float2 stores)
    const float* bias = biasbase + (size_t)z * Dd;
    float* C = Cbase + (size_t)z * M * Dd;
#pragma unroll
    for (int mt = 0; mt < 4; mt++)
#pragma unroll
        for (int nt = 0; nt < 4; nt++) {
            const int n = n0 + wn * 32 + nt * 8 + (lane & 3) * 2;
            const float2 bv = *(const float2*)&bias[n];
#pragma unroll
            for (int hf = 0; hf < 2; hf++) {
                const int m = m0 + wm * 64 + mt * 16 + (lane >> 2) + hf * 8;
                float2 v;
                v.x = scale * (acc[mt][nt][hf * 2 + 0] + bv.x);
                v.y = scale * (acc[mt][nt][hf * 2 + 1] + bv.y);
                if (mode == 0) {
                    const int b_ = m / T, t_ = m - b_ * T;
                    const int h = n >> 6, e = n & 63;
                    *(float2*)&C[((((size_t)(b_ * Hh + h)) * T + t_) << 6) + e] = v;
                } else {
                    *(float2*)&C[(size_t)m * Dd + n] = v;
                }
            }
        }
}

// ======================= flash attention (unchanged, passing) ===============
__global__ __launch_bounds__(256) void flash_kernel(
    const float* __restrict__ Q1,
    const float* __restrict__ Q2,
    const float* __restrict__ K1,
    const float* __restrict__ V1,
    const float* __restrict__ K2,
    const float* __restrict__ V2,
    const int* __restrict__ mask,
    float* __restrict__ out,
    int Tq)
{
    extern __shared__ __align__(16) float sm[];
    float* Qs   = sm;
    float* Ks   = Qs + 64 * SPAD;
    float* Vs   = Ks + 64 * SPAD;
    float* Ss   = Vs + 64 * 64;
    float* m_s  = Ss + 64 * SPAD;
    float* l_s  = m_s + 64;
    float* corr = l_s + 64;
    float* mflag = corr + 64;

    const int tid = threadIdx.x;
    const int tx = tid & 15;
    const int ty = tid >> 4;
    const int b = blockIdx.z, h = blockIdx.y, qt = blockIdx.x;

    const float* Q1p = Q1 + (((size_t)(b * Hh + h) * Tq) + qt * 64) * 64;
    const float* Q2p = Q2 + (((size_t)(b * Hh + h) * Tq) + qt * 64) * 64;
    const float* K1p = K1 + ((size_t)(b * Hh + h) * T1c) * 64;
    const float* V1p = V1 + ((size_t)(b * Hh + h) * T1c) * 64;
    const float* K2p = K2 + ((size_t)(b * Hh + h) * T2c) * 64;
    const float* V2p = V2 + ((size_t)(b * Hh + h) * T2c) * 64;

    for (int i = tid; i < 64 * 64; i += 256) {
        const int r = i >> 6, e = i & 63;
        Qs[e * SPAD + r] = Q1p[i];
    }
    for (int j = tid; j < T1c + T2c; j += 256)
        mflag[j] = (mask[b * (T1c + T2c) + j] != 0) ? 1.0f : 0.0f;
    if (tid < 64) { m_s[tid] = -1e30f; l_s[tid] = 0.0f; }

    float acc[4][4];
#pragma unroll
    for (int i = 0; i < 4; i++)
#pragma unroll
        for (int j = 0; j < 4; j++) acc[i][j] = 0.0f;

    for (int kt = 0; kt < 9; kt++) {
        const float* Kt;
        const float* Vt;
        int koff;
        if (kt < 8) { Kt = K1p + kt * 64 * 64; Vt = V1p + kt * 64 * 64; koff = kt * 64; }
        else        { Kt = K2p;               Vt = V2p;               koff = T1c; }

        __syncthreads();
        if (kt == 8) {
            for (int i = tid; i < 64 * 64; i += 256) {
                const int r = i >> 6, e = i & 63;
                Qs[e * SPAD + r] = Q2p[i];
            }
        }
        for (int i = tid; i < 64 * 64; i += 256) {
            const int j = i >> 6, e = i & 63;
            Ks[e * SPAD + j] = Kt[i];
        }
        for (int i = tid * 4; i < 64 * 64; i += 256 * 4)
            *(float4*)&Vs[i] = *(const float4*)&Vt[i];
        __syncthreads();

        float s[4][4];
#pragma unroll
        for (int i = 0; i < 4; i++)
#pragma unroll
            for (int j = 0; j < 4; j++) s[i][j] = 0.0f;
#pragma unroll 8
        for (int e = 0; e < 64; e++) {
            const float4 q  = *(const float4*)&Qs[e * SPAD + tx * 4];
            const float4 kv = *(const float4*)&Ks[e * SPAD + ty * 4];
            const float qa[4] = {q.x, q.y, q.z, q.w};
            const float ka[4] = {kv.x, kv.y, kv.z, kv.w};
#pragma unroll
            for (int i = 0; i < 4; i++)
#pragma unroll
                for (int j = 0; j < 4; j++)
                    s[i][j] += qa[i] * ka[j];
        }
#pragma unroll
        for (int jj = 0; jj < 4; jj++) {
            const float mf = mflag[koff + ty * 4 + jj];
            float4 v;
            v.x = (mf != 0.0f) ? NEGBIG : s[0][jj];
            v.y = (mf != 0.0f) ? NEGBIG : s[1][jj];
            v.z = (mf != 0.0f) ? NEGBIG : s[2][jj];
            v.w = (mf != 0.0f) ? NEGBIG : s[3][jj];
            *(float4*)&Ss[(ty * 4 + jj) * SPAD + tx * 4] = v;
        }
        __syncthreads();

        if (tid < 64) {
            const float mold = m_s[tid];
            float mx = mold;
            for (int j = 0; j < 64; j++) mx = fmaxf(mx, Ss[j * SPAD + tid]);
            const float c = __expf(mold - mx);
            float sum = 0.0f;
            for (int j = 0; j < 64; j++) {
                const float p = __expf(Ss[j * SPAD + tid] - mx);
                Ss[j * SPAD + tid] = p;
                sum += p;
            }
            l_s[tid] = l_s[tid] * c + sum;
            m_s[tid] = mx;
            corr[tid] = c;
        }
        __syncthreads();

        const float c0 = corr[tx * 4 + 0];
        const float c1 = corr[tx * 4 + 1];
        const float c2 = corr[tx * 4 + 2];
        const float c3 = corr[tx * 4 + 3];
#pragma unroll
        for (int j = 0; j < 4; j++) {
            acc[0][j] *= c0; acc[1][j] *= c1; acc[2][j] *= c2; acc[3][j] *= c3;
        }
#pragma unroll 8
        for (int kk = 0; kk < 64; kk++) {
            const float4 p = *(const float4*)&Ss[kk * SPAD + tx * 4];
            const float4 v = *(const float4*)&Vs[kk * 64 + ty * 4];
            const float pa[4] = {p.x, p.y, p.z, p.w};
            const float va[4] = {v.x, v.y, v.z, v.w};
#pragma unroll
            for (int i = 0; i < 4; i++)
#pragma unroll
                for (int j = 0; j < 4; j++)
                    acc[i][j] += pa[i] * va[j];
        }
    }

    __syncthreads();
#pragma unroll
    for (int ii = 0; ii < 4; ii++) {
        const int r = tx * 4 + ii;
        const float inv = 1.0f / l_s[r];
        const int row = qt * 64 + r;
        float4 o;
        o.x = acc[ii][0] * inv;
        o.y = acc[ii][1] * inv;
        o.z = acc[ii][2] * inv;
        o.w = acc[ii][3] * inv;
        *(float4*)&out[((size_t)b * Tq + row) * Dd + h * 64 + ty * 4] = o;
    }
}

// ======================= launch =============================================
extern "C" void kernel_launch(void* const* d_in, const int* in_sizes, int n_in,
                              void* d_out, int out_size)
{
    const float* feats = (const float*)d_in[0];
    const float* inps  = (const float*)d_in[1];
    const int*   mask  = (const int*)d_in[2];
    const float* W_f  = (const float*)d_in[3];
    const float* b_f  = (const float*)d_in[4];
    const float* W_i  = (const float*)d_in[5];
    const float* b_i  = (const float*)d_in[6];
    const float* Wu_v = (const float*)d_in[7];
    const float* bu_v = (const float*)d_in[8];
    const float* Wu_l = (const float*)d_in[9];
    const float* bu_l = (const float*)d_in[10];
    float* out = (float*)d_out;

    float *pf, *pi, *av, *al;
    cudaGetSymbolAddress((void**)&pf, g_proj_f);
    cudaGetSymbolAddress((void**)&pi, g_proj_i);
    cudaGetSymbolAddress((void**)&av, g_att_v);
    cudaGetSymbolAddress((void**)&al, g_att_l);
    __nv_bfloat16 *fh, *fl, *ih, *il, *wfh, *wfl, *wih, *wil;
    __nv_bfloat16 *wuvh, *wuvl, *wulh, *wull, *avh, *avl, *alh, *all_;
    cudaGetSymbolAddress((void**)&fh, g_fh);   cudaGetSymbolAddress((void**)&fl, g_fl);
    cudaGetSymbolAddress((void**)&ih, g_ih);   cudaGetSymbolAddress((void**)&il, g_il);
    cudaGetSymbolAddress((void**)&wfh, g_wfh); cudaGetSymbolAddress((void**)&wfl, g_wfl);
    cudaGetSymbolAddress((void**)&wih, g_wih); cudaGetSymbolAddress((void**)&wil, g_wil);
    cudaGetSymbolAddress((void**)&wuvh, g_wuvh); cudaGetSymbolAddress((void**)&wuvl, g_wuvl);
    cudaGetSymbolAddress((void**)&wulh, g_wulh); cudaGetSymbolAddress((void**)&wull, g_wull);
    cudaGetSymbolAddress((void**)&avh, g_avh); cudaGetSymbolAddress((void**)&avl, g_avl);
    cudaGetSymbolAddress((void**)&alh, g_alh); cudaGetSymbolAddress((void**)&all_, g_all);

    const size_t SF = (size_t)Bb * T1c * Dd;  // 6291456
    const size_t SI = (size_t)Bb * T2c * Dd;  // 786432
    const int NF = (int)SF, NI = (int)SI;

    cudaFuncSetAttribute(gemm_mma, cudaFuncAttributeMaxDynamicSharedMemorySize, GEMM_SMEM);
    const int fsm = (3 * 64 * SPAD + 64 * 64 + 3 * 64 + (T1c + T2c)) * (int)sizeof(float);
    cudaFuncSetAttribute(flash_kernel, cudaFuncAttributeMaxDynamicSharedMemorySize, fsm);

    // 1) fp32 -> bf16 hi/lo conversions
    conv_split<<<(NF + 255) / 256, 256>>>(feats, fh, fl, NF);
    conv_split<<<(NI + 255) / 256, 256>>>(inps, ih, il, NI);
    conv_wsplit<<<dim3(24, 24, 6), 256>>>(W_f, wfh, wfl);
    conv_wsplit<<<dim3(24, 24, 6), 256>>>(W_i, wih, wil);
    conv_wsplit<<<dim3(24, 24, 1), 256>>>(Wu_v, wuvh, wuvl);
    conv_wsplit<<<dim3(24, 24, 1), 256>>>(Wu_l, wulh, wull);

    // 2) projection GEMMs (tensor cores, split-bf16), scatter to [B][H][T][64]
    gemm_mma<<<dim3(6, 64, 6), 256, GEMM_SMEM>>>(fh, fl, wfh, wfl, b_f, pf,
                                                 Bb * T1c, T1c, PROJ_SCALE, 0);
    gemm_mma<<<dim3(6, 8, 6), 256, GEMM_SMEM>>>(ih, il, wih, wil, b_i, pi,
                                                Bb * T2c, T2c, PROJ_SCALE, 0);

    // 3) attention
    flash_kernel<<<dim3(8, Hh, Bb), 256, fsm>>>(
        pf + 1 * SF, pf + 3 * SF, pf + 0 * SF, pf + 2 * SF,
        pi + 0 * SI, pi + 1 * SI, mask, av, T1c);
    flash_kernel<<<dim3(1, Hh, Bb), 256, fsm>>>(
        pi + 2 * SI, pi + 3 * SI, pf + 4 * SF, pf + 5 * SF,
        pi + 4 * SI, pi + 5 * SI, mask, al, T2c);

    // 4) output projections
    conv_split<<<(NF + 255) / 256, 256>>>(av, avh, avl, NF);
    conv_split<<<(NI + 255) / 256, 256>>>(al, alh, all_, NI);
    gemm_mma<<<dim3(6, 64, 1), 256, GEMM_SMEM>>>(avh, avl, wuvh, wuvl, bu_v, out,
                                                 Bb * T1c, T1c, 1.0f, 1);
    gemm_mma<<<dim3(6, 8, 1), 256, GEMM_SMEM>>>(alh, all_, wulh, wull, bu_l, out + SF,
                                                Bb * T2c, T2c, 1.0f, 1);
}

// round 7
// speedup vs baseline: 2.1672x; 1.0640x over previous
#include <cuda_runtime.h>
#include <cuda_bf16.h>
#include <cstdint>
#include <math.h>

#define Hh 12
#define Dd 768
#define T1c 512
#define T2c 64
#define Bb 16
#define SPAD 68

static const float PROJ_SCALE = 0.3535533905932738f; // 64^-0.25
#define NEGBIG (-1e9f)

// ======================= PTX helpers (baseline ISA only) ====================
__device__ __forceinline__ uint32_t smem_to_u32(const void* p) {
    uint32_t a;
    asm("{ .reg .u64 t; cvta.to.shared.u64 t, %1; cvt.u32.u64 %0, t; }" : "=r"(a) : "l"(p));
    return a;
}
__device__ __forceinline__ void cp16(uint32_t saddr, const void* g) {
    // .ca: keep lines in L1 — A tiles reused by n-blocks, B tiles by m-blocks on same SM
    asm volatile("cp.async.ca.shared.global [%0], [%1], 16;" :: "r"(saddr), "l"(g));
}
__device__ __forceinline__ void ldsm4(uint32_t* r, uint32_t addr) {
    asm volatile("ldmatrix.sync.aligned.m8n8.x4.shared.b16 {%0,%1,%2,%3}, [%4];"
        : "=r"(r[0]), "=r"(r[1]), "=r"(r[2]), "=r"(r[3]) : "r"(addr));
}
__device__ __forceinline__ void mma_bf16(float* c, const uint32_t* a, const uint32_t* b) {
    asm volatile(
        "mma.sync.aligned.m16n8k16.row.col.f32.bf16.bf16.f32 "
        "{%0,%1,%2,%3}, {%4,%5,%6,%7}, {%8,%9}, {%0,%1,%2,%3};"
        : "+f"(c[0]), "+f"(c[1]), "+f"(c[2]), "+f"(c[3])
        : "r"(a[0]), "r"(a[1]), "r"(a[2]), "r"(a[3]), "r"(b[0]), "r"(b[1]));
}

// ======================= scratch (device globals) ===========================
__device__ float g_proj_f[6ull * Bb * T1c * Dd];   // [6][B][H][T1][64]
__device__ float g_proj_i[6ull * Bb * T2c * Dd];   // [6][B][H][T2][64]
__device__ float g_att_v[(size_t)Bb * T1c * Dd];   // [B][T1][768]
__device__ float g_att_l[(size_t)Bb * T2c * Dd];   // [B][T2][768]

__device__ __nv_bfloat16 g_fh[(size_t)Bb * T1c * Dd], g_fl[(size_t)Bb * T1c * Dd];
__device__ __nv_bfloat16 g_ih[(size_t)Bb * T2c * Dd], g_il[(size_t)Bb * T2c * Dd];
__device__ __nv_bfloat16 g_wfh[6ull * Dd * Dd], g_wfl[6ull * Dd * Dd];
__device__ __nv_bfloat16 g_wih[6ull * Dd * Dd], g_wil[6ull * Dd * Dd];
__device__ __nv_bfloat16 g_wuvh[(size_t)Dd * Dd], g_wuvl[(size_t)Dd * Dd];
__device__ __nv_bfloat16 g_wulh[(size_t)Dd * Dd], g_wull[(size_t)Dd * Dd];
__device__ __nv_bfloat16 g_avh[(size_t)Bb * T1c * Dd], g_avl[(size_t)Bb * T1c * Dd];
__device__ __nv_bfloat16 g_alh[(size_t)Bb * T2c * Dd], g_all[(size_t)Bb * T2c * Dd];

// ======================= conversion kernels =================================
__global__ __launch_bounds__(256) void conv_split(
    const float* __restrict__ x, __nv_bfloat16* __restrict__ hi,
    __nv_bfloat16* __restrict__ lo, int n)
{
    int i = blockIdx.x * 256 + threadIdx.x;
    if (i < n) {
        float v = x[i];
        __nv_bfloat16 h = __float2bfloat16(v);
        hi[i] = h;
        lo[i] = __float2bfloat16(v - __bfloat162float(h));
    }
}

// W [z][K=768][N=768] -> out[z][N][K] hi/lo (K-major B operand)
__global__ __launch_bounds__(256) void conv_wsplit(
    const float* __restrict__ W, __nv_bfloat16* __restrict__ bh,
    __nv_bfloat16* __restrict__ bl)
{
    __shared__ float t[32][33];
    const float* Wz = W + (size_t)blockIdx.z * Dd * Dd;
    const int k0 = blockIdx.y * 32, n0 = blockIdx.x * 32;
    const int tx = threadIdx.x & 31, ty = threadIdx.x >> 5; // 32 x 8
#pragma unroll
    for (int j = 0; j < 32; j += 8)
        t[ty + j][tx] = Wz[(size_t)(k0 + ty + j) * Dd + n0 + tx];
    __syncthreads();
#pragma unroll
    for (int j = 0; j < 32; j += 8) {
        float v = t[tx][ty + j];  // = W[k0+tx][n0+ty+j]
        size_t o = (size_t)blockIdx.z * Dd * Dd + (size_t)(n0 + ty + j) * Dd + k0 + tx;
        __nv_bfloat16 h = __float2bfloat16(v);
        bh[o] = h;
        bl[o] = __float2bfloat16(v - __bfloat162float(h));
    }
}

// ======================= mma.sync split-bf16 GEMM ===========================
// C = A[M,768] @ W[768,768] (+bias)(*scale); A/W as bf16 hi+lo.
// B operand K-major [z][N][K]. Tile 128x128, BK=32, double-buffered cp.async.
// 8 warps: warp tile 64x32 (wm = wid&1, wn = wid>>1), m16n8k16 4x4 per warp.
// Split product: Ah*Bh + Ah*Bl + Al*Bh  (3 MMAs per fragment pair).
// B fragment: SMEM [n][k] row-major IS col-major kxn -> ldmatrix WITHOUT trans.
// __launch_bounds__(256,2): cap regs at 124 so 2 CTAs/SM co-reside (160KB smem)
// -> cross-block overlap hides sync/cp.async drain of the tensor pipe.
#define ROWB 80                 // 32 bf16 + 8 pad = 40 elems = 80 bytes/row
#define TILE_B (128 * ROWB)     // 10240
#define STAGE_B (4 * TILE_B)    // 40960: [Ah | Al | Bh | Bl]
#define GEMM_SMEM (2 * STAGE_B) // 81920

__global__ __launch_bounds__(256, 2) void gemm_mma(
    const __nv_bfloat16* __restrict__ Ah, const __nv_bfloat16* __restrict__ Al,
    const __nv_bfloat16* __restrict__ Bh, const __nv_bfloat16* __restrict__ Bl,
    const float* __restrict__ biasbase, float* __restrict__ Cbase,
    int M, int T, float scale, int mode)
{
    extern __shared__ __align__(16) char smem[];
    const uint32_t sb = smem_to_u32(smem);
    const int tid = threadIdx.x, lane = tid & 31, wid = tid >> 5;
    const int wm = wid & 1, wn = wid >> 1;
    const int z = blockIdx.z;
    const int m0 = blockIdx.y * 128, n0 = blockIdx.x * 128;

    const __nv_bfloat16* srcs[4];
    srcs[0] = Ah; srcs[1] = Al;
    srcs[2] = Bh + (size_t)z * Dd * Dd; srcs[3] = Bl + (size_t)z * Dd * Dd;

    float acc[4][4][4];
#pragma unroll
    for (int a = 0; a < 4; a++)
#pragma unroll
        for (int b = 0; b < 4; b++)
#pragma unroll
            for (int c = 0; c < 4; c++) acc[a][b][c] = 0.0f;

#define LOAD_STAGE(kc, s) do {                                                \
    _Pragma("unroll")                                                         \
    for (int t_ = 0; t_ < 4; t_++) {                                          \
        const __nv_bfloat16* src_ = srcs[t_];                                 \
        const int rowbase_ = (t_ < 2) ? m0 : n0;                              \
        _Pragma("unroll")                                                     \
        for (int u_ = 0; u_ < 2; u_++) {                                      \
            const int idx_ = tid * 2 + u_;                                    \
            const int row_ = idx_ >> 2, cc_ = idx_ & 3;                       \
            cp16(sb + (s) * STAGE_B + t_ * TILE_B + row_ * ROWB + cc_ * 16,   \
                 src_ + (size_t)(rowbase_ + row_) * Dd + (kc) * 32 + cc_ * 8);\
        }                                                                     \
    }                                                                         \
    asm volatile("cp.async.commit_group;" ::: "memory");                      \
} while (0)

    LOAD_STAGE(0, 0);

    for (int i = 0; i < 24; i++) {
        const int s = i & 1;
        if (i + 1 < 24) {
            LOAD_STAGE(i + 1, s ^ 1);
            asm volatile("cp.async.wait_group 1;" ::: "memory");
        } else {
            asm volatile("cp.async.wait_group 0;" ::: "memory");
        }
        __syncthreads();

        const uint32_t st = sb + s * STAGE_B;
#pragma unroll
        for (int ks = 0; ks < 2; ks++) {
            const int kb = ks * 32;   // byte offset along K within the row
            uint32_t bh[4][2], bl[4][2];
#pragma unroll
            for (int p = 0; p < 2; p++) {
                uint32_t r[4];
                uint32_t ab = st + 2 * TILE_B +
                              (wn * 32 + p * 16 + (lane & 15)) * ROWB +
                              ((lane >> 4) * 16) + kb;
                ldsm4(r, ab);                      // non-trans: [n][k] == col-major kxn
                bh[p * 2][0] = r[0]; bh[p * 2 + 1][0] = r[1];
                bh[p * 2][1] = r[2]; bh[p * 2 + 1][1] = r[3];
                ldsm4(r, ab + TILE_B);
                bl[p * 2][0] = r[0]; bl[p * 2 + 1][0] = r[1];
                bl[p * 2][1] = r[2]; bl[p * 2 + 1][1] = r[3];
            }
            uint32_t a[4][4];
#pragma unroll
            for (int mt = 0; mt < 4; mt++)
                ldsm4(a[mt], st + (wm * 64 + mt * 16 + (lane & 15)) * ROWB +
                             ((lane >> 4) * 16) + kb);
#pragma unroll
            for (int mt = 0; mt < 4; mt++)
#pragma unroll
                for (int nt = 0; nt < 4; nt++) {
                    mma_bf16(acc[mt][nt], a[mt], bh[nt]);
                    mma_bf16(acc[mt][nt], a[mt], bl[nt]);
                }
#pragma unroll
            for (int mt = 0; mt < 4; mt++)
                ldsm4(a[mt], st + TILE_B + (wm * 64 + mt * 16 + (lane & 15)) * ROWB +
                             ((lane >> 4) * 16) + kb);
#pragma unroll
            for (int mt = 0; mt < 4; mt++)
#pragma unroll
                for (int nt = 0; nt < 4; nt++)
                    mma_bf16(acc[mt][nt], a[mt], bh[nt]);
        }
        __syncthreads();
    }

    // epilogue: fragment -> global (float2 stores)
    const float* bias = biasbase + (size_t)z * Dd;
    float* C = Cbase + (size_t)z * M * Dd;
#pragma unroll
    for (int mt = 0; mt < 4; mt++)
#pragma unroll
        for (int nt = 0; nt < 4; nt++) {
            const int n = n0 + wn * 32 + nt * 8 + (lane & 3) * 2;
            const float2 bv = *(const float2*)&bias[n];
#pragma unroll
            for (int hf = 0; hf < 2; hf++) {
                const int m = m0 + wm * 64 + mt * 16 + (lane >> 2) + hf * 8;
                float2 v;
                v.x = scale * (acc[mt][nt][hf * 2 + 0] + bv.x);
                v.y = scale * (acc[mt][nt][hf * 2 + 1] + bv.y);
                if (mode == 0) {
                    const int b_ = m / T, t_ = m - b_ * T;
                    const int h = n >> 6, e = n & 63;
                    *(float2*)&C[((((size_t)(b_ * Hh + h)) * T + t_) << 6) + e] = v;
                } else {
                    *(float2*)&C[(size_t)m * Dd + n] = v;
                }
            }
        }
}

// ======================= flash attention (unchanged, passing) ===============
__global__ __launch_bounds__(256) void flash_kernel(
    const float* __restrict__ Q1,
    const float* __restrict__ Q2,
    const float* __restrict__ K1,
    const float* __restrict__ V1,
    const float* __restrict__ K2,
    const float* __restrict__ V2,
    const int* __restrict__ mask,
    float* __restrict__ out,
    int Tq)
{
    extern __shared__ __align__(16) float sm[];
    float* Qs   = sm;
    float* Ks   = Qs + 64 * SPAD;
    float* Vs   = Ks + 64 * SPAD;
    float* Ss   = Vs + 64 * 64;
    float* m_s  = Ss + 64 * SPAD;
    float* l_s  = m_s + 64;
    float* corr = l_s + 64;
    float* mflag = corr + 64;

    const int tid = threadIdx.x;
    const int tx = tid & 15;
    const int ty = tid >> 4;
    const int b = blockIdx.z, h = blockIdx.y, qt = blockIdx.x;

    const float* Q1p = Q1 + (((size_t)(b * Hh + h) * Tq) + qt * 64) * 64;
    const float* Q2p = Q2 + (((size_t)(b * Hh + h) * Tq) + qt * 64) * 64;
    const float* K1p = K1 + ((size_t)(b * Hh + h) * T1c) * 64;
    const float* V1p = V1 + ((size_t)(b * Hh + h) * T1c) * 64;
    const float* K2p = K2 + ((size_t)(b * Hh + h) * T2c) * 64;
    const float* V2p = V2 + ((size_t)(b * Hh + h) * T2c) * 64;

    for (int i = tid; i < 64 * 64; i += 256) {
        const int r = i >> 6, e = i & 63;
        Qs[e * SPAD + r] = Q1p[i];
    }
    for (int j = tid; j < T1c + T2c; j += 256)
        mflag[j] = (mask[b * (T1c + T2c) + j] != 0) ? 1.0f : 0.0f;
    if (tid < 64) { m_s[tid] = -1e30f; l_s[tid] = 0.0f; }

    float acc[4][4];
#pragma unroll
    for (int i = 0; i < 4; i++)
#pragma unroll
        for (int j = 0; j < 4; j++) acc[i][j] = 0.0f;

    for (int kt = 0; kt < 9; kt++) {
        const float* Kt;
        const float* Vt;
        int koff;
        if (kt < 8) { Kt = K1p + kt * 64 * 64; Vt = V1p + kt * 64 * 64; koff = kt * 64; }
        else        { Kt = K2p;               Vt = V2p;               koff = T1c; }

        __syncthreads();
        if (kt == 8) {
            for (int i = tid; i < 64 * 64; i += 256) {
                const int r = i >> 6, e = i & 63;
                Qs[e * SPAD + r] = Q2p[i];
            }
        }
        for (int i = tid; i < 64 * 64; i += 256) {
            const int j = i >> 6, e = i & 63;
            Ks[e * SPAD + j] = Kt[i];
        }
        for (int i = tid * 4; i < 64 * 64; i += 256 * 4)
            *(float4*)&Vs[i] = *(const float4*)&Vt[i];
        __syncthreads();

        float s[4][4];
#pragma unroll
        for (int i = 0; i < 4; i++)
#pragma unroll
            for (int j = 0; j < 4; j++) s[i][j] = 0.0f;
#pragma unroll 8
        for (int e = 0; e < 64; e++) {
            const float4 q  = *(const float4*)&Qs[e * SPAD + tx * 4];
            const float4 kv = *(const float4*)&Ks[e * SPAD + ty * 4];
            const float qa[4] = {q.x, q.y, q.z, q.w};
            const float ka[4] = {kv.x, kv.y, kv.z, kv.w};
#pragma unroll
            for (int i = 0; i < 4; i++)
#pragma unroll
                for (int j = 0; j < 4; j++)
                    s[i][j] += qa[i] * ka[j];
        }
#pragma unroll
        for (int jj = 0; jj < 4; jj++) {
            const float mf = mflag[koff + ty * 4 + jj];
            float4 v;
            v.x = (mf != 0.0f) ? NEGBIG : s[0][jj];
            v.y = (mf != 0.0f) ? NEGBIG : s[1][jj];
            v.z = (mf != 0.0f) ? NEGBIG : s[2][jj];
            v.w = (mf != 0.0f) ? NEGBIG : s[3][jj];
            *(float4*)&Ss[(ty * 4 + jj) * SPAD + tx * 4] = v;
        }
        __syncthreads();

        if (tid < 64) {
            const float mold = m_s[tid];
            float mx = mold;
            for (int j = 0; j < 64; j++) mx = fmaxf(mx, Ss[j * SPAD + tid]);
            const float c = __expf(mold - mx);
            float sum = 0.0f;
            for (int j = 0; j < 64; j++) {
                const float p = __expf(Ss[j * SPAD + tid] - mx);
                Ss[j * SPAD + tid] = p;
                sum += p;
            }
            l_s[tid] = l_s[tid] * c + sum;
            m_s[tid] = mx;
            corr[tid] = c;
        }
        __syncthreads();

        const float c0 = corr[tx * 4 + 0];
        const float c1 = corr[tx * 4 + 1];
        const float c2 = corr[tx * 4 + 2];
        const float c3 = corr[tx * 4 + 3];
#pragma unroll
        for (int j = 0; j < 4; j++) {
            acc[0][j] *= c0; acc[1][j] *= c1; acc[2][j] *= c2; acc[3][j] *= c3;
        }
#pragma unroll 8
        for (int kk = 0; kk < 64; kk++) {
            const float4 p = *(const float4*)&Ss[kk * SPAD + tx * 4];
            const float4 v = *(const float4*)&Vs[kk * 64 + ty * 4];
            const float pa[4] = {p.x, p.y, p.z, p.w};
            const float va[4] = {v.x, v.y, v.z, v.w};
#pragma unroll
            for (int i = 0; i < 4; i++)
#pragma unroll
                for (int j = 0; j < 4; j++)
                    acc[i][j] += pa[i] * va[j];
        }
    }

    __syncthreads();
#pragma unroll
    for (int ii = 0; ii < 4; ii++) {
        const int r = tx * 4 + ii;
        const float inv = 1.0f / l_s[r];
        const int row = qt * 64 + r;
        float4 o;
        o.x = acc[ii][0] * inv;
        o.y = acc[ii][1] * inv;
        o.z = acc[ii][2] * inv;
        o.w = acc[ii][3] * inv;
        *(float4*)&out[((size_t)b * Tq + row) * Dd + h * 64 + ty * 4] = o;
    }
}

// ======================= launch =============================================
extern "C" void kernel_launch(void* const* d_in, const int* in_sizes, int n_in,
                              void* d_out, int out_size)
{
    const float* feats = (const float*)d_in[0];
    const float* inps  = (const float*)d_in[1];
    const int*   mask  = (const int*)d_in[2];
    const float* W_f  = (const float*)d_in[3];
    const float* b_f  = (const float*)d_in[4];
    const float* W_i  = (const float*)d_in[5];
    const float* b_i  = (const float*)d_in[6];
    const float* Wu_v = (const float*)d_in[7];
    const float* bu_v = (const float*)d_in[8];
    const float* Wu_l = (const float*)d_in[9];
    const float* bu_l = (const float*)d_in[10];
    float* out = (float*)d_out;

    float *pf, *pi, *av, *al;
    cudaGetSymbolAddress((void**)&pf, g_proj_f);
    cudaGetSymbolAddress((void**)&pi, g_proj_i);
    cudaGetSymbolAddress((void**)&av, g_att_v);
    cudaGetSymbolAddress((void**)&al, g_att_l);
    __nv_bfloat16 *fh, *fl, *ih, *il, *wfh, *wfl, *wih, *wil;
    __nv_bfloat16 *wuvh, *wuvl, *wulh, *wull, *avh, *avl, *alh, *all_;
    cudaGetSymbolAddress((void**)&fh, g_fh);   cudaGetSymbolAddress((void**)&fl, g_fl);
    cudaGetSymbolAddress((void**)&ih, g_ih);   cudaGetSymbolAddress((void**)&il, g_il);
    cudaGetSymbolAddress((void**)&wfh, g_wfh); cudaGetSymbolAddress((void**)&wfl, g_wfl);
    cudaGetSymbolAddress((void**)&wih, g_wih); cudaGetSymbolAddress((void**)&wil, g_wil);
    cudaGetSymbolAddress((void**)&wuvh, g_wuvh); cudaGetSymbolAddress((void**)&wuvl, g_wuvl);
    cudaGetSymbolAddress((void**)&wulh, g_wulh); cudaGetSymbolAddress((void**)&wull, g_wull);
    cudaGetSymbolAddress((void**)&avh, g_avh); cudaGetSymbolAddress((void**)&avl, g_avl);
    cudaGetSymbolAddress((void**)&alh, g_alh); cudaGetSymbolAddress((void**)&all_, g_all);

    const size_t SF = (size_t)Bb * T1c * Dd;  // 6291456
    const size_t SI = (size_t)Bb * T2c * Dd;  // 786432
    const int NF = (int)SF, NI = (int)SI;

    cudaFuncSetAttribute(gemm_mma, cudaFuncAttributeMaxDynamicSharedMemorySize, GEMM_SMEM);
    const int fsm = (3 * 64 * SPAD + 64 * 64 + 3 * 64 + (T1c + T2c)) * (int)sizeof(float);
    cudaFuncSetAttribute(flash_kernel, cudaFuncAttributeMaxDynamicSharedMemorySize, fsm);

    // 1) fp32 -> bf16 hi/lo conversions
    conv_split<<<(NF + 255) / 256, 256>>>(feats, fh, fl, NF);
    conv_split<<<(NI + 255) / 256, 256>>>(inps, ih, il, NI);
    conv_wsplit<<<dim3(24, 24, 6), 256>>>(W_f, wfh, wfl);
    conv_wsplit<<<dim3(24, 24, 6), 256>>>(W_i, wih, wil);
    conv_wsplit<<<dim3(24, 24, 1), 256>>>(Wu_v, wuvh, wuvl);
    conv_wsplit<<<dim3(24, 24, 1), 256>>>(Wu_l, wulh, wull);

    // 2) projection GEMMs (tensor cores, split-bf16), scatter to [B][H][T][64]
    gemm_mma<<<dim3(6, 64, 6), 256, GEMM_SMEM>>>(fh, fl, wfh, wfl, b_f, pf,
                                                 Bb * T1c, T1c, PROJ_SCALE, 0);
    gemm_mma<<<dim3(6, 8, 6), 256, GEMM_SMEM>>>(ih, il, wih, wil, b_i, pi,
                                                Bb * T2c, T2c, PROJ_SCALE, 0);

    // 3) attention
    flash_kernel<<<dim3(8, Hh, Bb), 256, fsm>>>(
        pf + 1 * SF, pf + 3 * SF, pf + 0 * SF, pf + 2 * SF,
        pi + 0 * SI, pi + 1 * SI, mask, av, T1c);
    flash_kernel<<<dim3(1, Hh, Bb), 256, fsm>>>(
        pi + 2 * SI, pi + 3 * SI, pf + 4 * SF, pf + 5 * SF,
        pi + 4 * SI, pi + 5 * SI, mask, al, T2c);

    // 4) output projections
    conv_split<<<(NF + 255) / 256, 256>>>(av, avh, avl, NF);
    conv_split<<<(NI + 255) / 256, 256>>>(al, alh, all_, NI);
    gemm_mma<<<dim3(6, 64, 1), 256, GEMM_SMEM>>>(avh, avl, wuvh, wuvl, bu_v, out,
                                                 Bb * T1c, T1c, 1.0f, 1);
    gemm_mma<<<dim3(6, 8, 1), 256, GEMM_SMEM>>>(alh, all_, wulh, wull, bu_l, out + SF,
                                                Bb * T2c, T2c, 1.0f, 1);
}

// round 8
// speedup vs baseline: 2.1954x; 1.0130x over previous
#include <cuda_runtime.h>
#include <cuda_bf16.h>
#include <cstdint>
#include <math.h>

#define Hh 12
#define Dd 768
#define T1c 512
#define T2c 64
#define Bb 16
#define SPAD 68

static const float PROJ_SCALE = 0.3535533905932738f; // 64^-0.25
#define NEGBIG (-1e9f)

// ======================= PTX helpers (baseline ISA only) ====================
__device__ __forceinline__ uint32_t smem_to_u32(const void* p) {
    uint32_t a;
    asm("{ .reg .u64 t; cvta.to.shared.u64 t, %1; cvt.u32.u64 %0, t; }" : "=r"(a) : "l"(p));
    return a;
}
__device__ __forceinline__ void cp16(uint32_t saddr, const void* g) {
    asm volatile("cp.async.ca.shared.global [%0], [%1], 16;" :: "r"(saddr), "l"(g));
}
__device__ __forceinline__ void ldsm4(uint32_t* r, uint32_t addr) {
    asm volatile("ldmatrix.sync.aligned.m8n8.x4.shared.b16 {%0,%1,%2,%3}, [%4];"
        : "=r"(r[0]), "=r"(r[1]), "=r"(r[2]), "=r"(r[3]) : "r"(addr));
}
__device__ __forceinline__ void mma_bf16(float* c, const uint32_t* a, const uint32_t* b) {
    asm volatile(
        "mma.sync.aligned.m16n8k16.row.col.f32.bf16.bf16.f32 "
        "{%0,%1,%2,%3}, {%4,%5,%6,%7}, {%8,%9}, {%0,%1,%2,%3};"
        : "+f"(c[0]), "+f"(c[1]), "+f"(c[2]), "+f"(c[3])
        : "r"(a[0]), "r"(a[1]), "r"(a[2]), "r"(a[3]), "r"(b[0]), "r"(b[1]));
}

// ======================= scratch (device globals) ===========================
__device__ float g_proj_f[6ull * Bb * T1c * Dd];   // [6][B][H][T1][64]
__device__ float g_proj_i[6ull * Bb * T2c * Dd];   // [6][B][H][T2][64]

__device__ __nv_bfloat16 g_fh[(size_t)Bb * T1c * Dd], g_fl[(size_t)Bb * T1c * Dd];
__device__ __nv_bfloat16 g_ih[(size_t)Bb * T2c * Dd], g_il[(size_t)Bb * T2c * Dd];
__device__ __nv_bfloat16 g_wfh[6ull * Dd * Dd], g_wfl[6ull * Dd * Dd];
__device__ __nv_bfloat16 g_wih[6ull * Dd * Dd], g_wil[6ull * Dd * Dd];
__device__ __nv_bfloat16 g_wuvh[(size_t)Dd * Dd], g_wuvl[(size_t)Dd * Dd];
__device__ __nv_bfloat16 g_wulh[(size_t)Dd * Dd], g_wull[(size_t)Dd * Dd];
__device__ __nv_bfloat16 g_avh[(size_t)Bb * T1c * Dd], g_avl[(size_t)Bb * T1c * Dd];
__device__ __nv_bfloat16 g_alh[(size_t)Bb * T2c * Dd], g_all[(size_t)Bb * T2c * Dd];

// ======================= conversion kernels =================================
__global__ __launch_bounds__(256) void conv_split(
    const float* __restrict__ x, __nv_bfloat16* __restrict__ hi,
    __nv_bfloat16* __restrict__ lo, int n)
{
    int i = blockIdx.x * 256 + threadIdx.x;
    if (i < n) {
        float v = x[i];
        __nv_bfloat16 h = __float2bfloat16(v);
        hi[i] = h;
        lo[i] = __float2bfloat16(v - __bfloat162float(h));
    }
}

// W [z][K=768][N=768] -> out[z][N][K] hi/lo (K-major B operand)
__global__ __launch_bounds__(256) void conv_wsplit(
    const float* __restrict__ W, __nv_bfloat16* __restrict__ bh,
    __nv_bfloat16* __restrict__ bl)
{
    __shared__ float t[32][33];
    const float* Wz = W + (size_t)blockIdx.z * Dd * Dd;
    const int k0 = blockIdx.y * 32, n0 = blockIdx.x * 32;
    const int tx = threadIdx.x & 31, ty = threadIdx.x >> 5; // 32 x 8
#pragma unroll
    for (int j = 0; j < 32; j += 8)
        t[ty + j][tx] = Wz[(size_t)(k0 + ty + j) * Dd + n0 + tx];
    __syncthreads();
#pragma unroll
    for (int j = 0; j < 32; j += 8) {
        float v = t[tx][ty + j];  // = W[k0+tx][n0+ty+j]
        size_t o = (size_t)blockIdx.z * Dd * Dd + (size_t)(n0 + ty + j) * Dd + k0 + tx;
        __nv_bfloat16 h = __float2bfloat16(v);
        bh[o] = h;
        bl[o] = __float2bfloat16(v - __bfloat162float(h));
    }
}

// Two single matrices (Wu_v, Wu_l) in one launch: z=0 -> (W1,bh1,bl1), z=1 -> (W2,...)
__global__ __launch_bounds__(256) void conv_wsplit2(
    const float* __restrict__ W1, __nv_bfloat16* __restrict__ bh1, __nv_bfloat16* __restrict__ bl1,
    const float* __restrict__ W2, __nv_bfloat16* __restrict__ bh2, __nv_bfloat16* __restrict__ bl2)
{
    __shared__ float t[32][33];
    const float* Wz = (blockIdx.z == 0) ? W1 : W2;
    __nv_bfloat16* bh = (blockIdx.z == 0) ? bh1 : bh2;
    __nv_bfloat16* bl = (blockIdx.z == 0) ? bl1 : bl2;
    const int k0 = blockIdx.y * 32, n0 = blockIdx.x * 32;
    const int tx = threadIdx.x & 31, ty = threadIdx.x >> 5;
#pragma unroll
    for (int j = 0; j < 32; j += 8)
        t[ty + j][tx] = Wz[(size_t)(k0 + ty + j) * Dd + n0 + tx];
    __syncthreads();
#pragma unroll
    for (int j = 0; j < 32; j += 8) {
        float v = t[tx][ty + j];
        size_t o = (size_t)(n0 + ty + j) * Dd + k0 + tx;
        __nv_bfloat16 h = __float2bfloat16(v);
        bh[o] = h;
        bl[o] = __float2bfloat16(v - __bfloat162float(h));
    }
}

// ======================= mma.sync split-bf16 GEMM (unchanged) ===============
#define ROWB 80                 // 32 bf16 + 8 pad = 40 elems = 80 bytes/row
#define TILE_B (128 * ROWB)     // 10240
#define STAGE_B (4 * TILE_B)    // 40960: [Ah | Al | Bh | Bl]
#define GEMM_SMEM (2 * STAGE_B) // 81920

__global__ __launch_bounds__(256, 2) void gemm_mma(
    const __nv_bfloat16* __restrict__ Ah, const __nv_bfloat16* __restrict__ Al,
    const __nv_bfloat16* __restrict__ Bh, const __nv_bfloat16* __restrict__ Bl,
    const float* __restrict__ biasbase, float* __restrict__ Cbase,
    int M, int T, float scale, int mode)
{
    extern __shared__ __align__(16) char smem[];
    const uint32_t sb = smem_to_u32(smem);
    const int tid = threadIdx.x, lane = tid & 31, wid = tid >> 5;
    const int wm = wid & 1, wn = wid >> 1;
    const int z = blockIdx.z;
    const int m0 = blockIdx.y * 128, n0 = blockIdx.x * 128;

    const __nv_bfloat16* srcs[4];
    srcs[0] = Ah; srcs[1] = Al;
    srcs[2] = Bh + (size_t)z * Dd * Dd; srcs[3] = Bl + (size_t)z * Dd * Dd;

    float acc[4][4][4];
#pragma unroll
    for (int a = 0; a < 4; a++)
#pragma unroll
        for (int b = 0; b < 4; b++)
#pragma unroll
            for (int c = 0; c < 4; c++) acc[a][b][c] = 0.0f;

#define LOAD_STAGE(kc, s) do {                                                \
    _Pragma("unroll")                                                         \
    for (int t_ = 0; t_ < 4; t_++) {                                          \
        const __nv_bfloat16* src_ = srcs[t_];                                 \
        const int rowbase_ = (t_ < 2) ? m0 : n0;                              \
        _Pragma("unroll")                                                     \
        for (int u_ = 0; u_ < 2; u_++) {                                      \
            const int idx_ = tid * 2 + u_;                                    \
            const int row_ = idx_ >> 2, cc_ = idx_ & 3;                       \
            cp16(sb + (s) * STAGE_B + t_ * TILE_B + row_ * ROWB + cc_ * 16,   \
                 src_ + (size_t)(rowbase_ + row_) * Dd + (kc) * 32 + cc_ * 8);\
        }                                                                     \
    }                                                                         \
    asm volatile("cp.async.commit_group;" ::: "memory");                      \
} while (0)

    LOAD_STAGE(0, 0);

    for (int i = 0; i < 24; i++) {
        const int s = i & 1;
        if (i + 1 < 24) {
            LOAD_STAGE(i + 1, s ^ 1);
            asm volatile("cp.async.wait_group 1;" ::: "memory");
        } else {
            asm volatile("cp.async.wait_group 0;" ::: "memory");
        }
        __syncthreads();

        const uint32_t st = sb + s * STAGE_B;
#pragma unroll
        for (int ks = 0; ks < 2; ks++) {
            const int kb = ks * 32;   // byte offset along K within the row
            uint32_t bh[4][2], bl[4][2];
#pragma unroll
            for (int p = 0; p < 2; p++) {
                uint32_t r[4];
                uint32_t ab = st + 2 * TILE_B +
                              (wn * 32 + p * 16 + (lane & 15)) * ROWB +
                              ((lane >> 4) * 16) + kb;
                ldsm4(r, ab);                      // non-trans: [n][k] == col-major kxn
                bh[p * 2][0] = r[0]; bh[p * 2 + 1][0] = r[1];
                bh[p * 2][1] = r[2]; bh[p * 2 + 1][1] = r[3];
                ldsm4(r, ab + TILE_B);
                bl[p * 2][0] = r[0]; bl[p * 2 + 1][0] = r[1];
                bl[p * 2][1] = r[2]; bl[p * 2 + 1][1] = r[3];
            }
            uint32_t a[4][4];
#pragma unroll
            for (int mt = 0; mt < 4; mt++)
                ldsm4(a[mt], st + (wm * 64 + mt * 16 + (lane & 15)) * ROWB +
                             ((lane >> 4) * 16) + kb);
#pragma unroll
            for (int mt = 0; mt < 4; mt++)
#pragma unroll
                for (int nt = 0; nt < 4; nt++) {
                    mma_bf16(acc[mt][nt], a[mt], bh[nt]);
                    mma_bf16(acc[mt][nt], a[mt], bl[nt]);
                }
#pragma unroll
            for (int mt = 0; mt < 4; mt++)
                ldsm4(a[mt], st + TILE_B + (wm * 64 + mt * 16 + (lane & 15)) * ROWB +
                             ((lane >> 4) * 16) + kb);
#pragma unroll
            for (int mt = 0; mt < 4; mt++)
#pragma unroll
                for (int nt = 0; nt < 4; nt++)
                    mma_bf16(acc[mt][nt], a[mt], bh[nt]);
        }
        __syncthreads();
    }

    // epilogue: fragment -> global (float2 stores)
    const float* bias = biasbase + (size_t)z * Dd;
    float* C = Cbase + (size_t)z * M * Dd;
#pragma unroll
    for (int mt = 0; mt < 4; mt++)
#pragma unroll
        for (int nt = 0; nt < 4; nt++) {
            const int n = n0 + wn * 32 + nt * 8 + (lane & 3) * 2;
            const float2 bv = *(const float2*)&bias[n];
#pragma unroll
            for (int hf = 0; hf < 2; hf++) {
                const int m = m0 + wm * 64 + mt * 16 + (lane >> 2) + hf * 8;
                float2 v;
                v.x = scale * (acc[mt][nt][hf * 2 + 0] + bv.x);
                v.y = scale * (acc[mt][nt][hf * 2 + 1] + bv.y);
                if (mode == 0) {
                    const int b_ = m / T, t_ = m - b_ * T;
                    const int h = n >> 6, e = n & 63;
                    *(float2*)&C[((((size_t)(b_ * Hh + h)) * T + t_) << 6) + e] = v;
                } else {
                    *(float2*)&C[(size_t)m * Dd + n] = v;
                }
            }
        }
}

// ======================= flash attention (epilogue now emits bf16 hi/lo) ====
__global__ __launch_bounds__(256) void flash_kernel(
    const float* __restrict__ Q1,
    const float* __restrict__ Q2,
    const float* __restrict__ K1,
    const float* __restrict__ V1,
    const float* __restrict__ K2,
    const float* __restrict__ V2,
    const int* __restrict__ mask,
    __nv_bfloat16* __restrict__ outh,
    __nv_bfloat16* __restrict__ outl,
    int Tq)
{
    extern __shared__ __align__(16) float sm[];
    float* Qs   = sm;
    float* Ks   = Qs + 64 * SPAD;
    float* Vs   = Ks + 64 * SPAD;
    float* Ss   = Vs + 64 * 64;
    float* m_s  = Ss + 64 * SPAD;
    float* l_s  = m_s + 64;
    float* corr = l_s + 64;
    float* mflag = corr + 64;

    const int tid = threadIdx.x;
    const int tx = tid & 15;
    const int ty = tid >> 4;
    const int b = blockIdx.z, h = blockIdx.y, qt = blockIdx.x;

    const float* Q1p = Q1 + (((size_t)(b * Hh + h) * Tq) + qt * 64) * 64;
    const float* Q2p = Q2 + (((size_t)(b * Hh + h) * Tq) + qt * 64) * 64;
    const float* K1p = K1 + ((size_t)(b * Hh + h) * T1c) * 64;
    const float* V1p = V1 + ((size_t)(b * Hh + h) * T1c) * 64;
    const float* K2p = K2 + ((size_t)(b * Hh + h) * T2c) * 64;
    const float* V2p = V2 + ((size_t)(b * Hh + h) * T2c) * 64;

    for (int i = tid; i < 64 * 64; i += 256) {
        const int r = i >> 6, e = i & 63;
        Qs[e * SPAD + r] = Q1p[i];
    }
    for (int j = tid; j < T1c + T2c; j += 256)
        mflag[j] = (mask[b * (T1c + T2c) + j] != 0) ? 1.0f : 0.0f;
    if (tid < 64) { m_s[tid] = -1e30f; l_s[tid] = 0.0f; }

    float acc[4][4];
#pragma unroll
    for (int i = 0; i < 4; i++)
#pragma unroll
        for (int j = 0; j < 4; j++) acc[i][j] = 0.0f;

    for (int kt = 0; kt < 9; kt++) {
        const float* Kt;
        const float* Vt;
        int koff;
        if (kt < 8) { Kt = K1p + kt * 64 * 64; Vt = V1p + kt * 64 * 64; koff = kt * 64; }
        else        { Kt = K2p;               Vt = V2p;               koff = T1c; }

        __syncthreads();
        if (kt == 8) {
            for (int i = tid; i < 64 * 64; i += 256) {
                const int r = i >> 6, e = i & 63;
                Qs[e * SPAD + r] = Q2p[i];
            }
        }
        for (int i = tid; i < 64 * 64; i += 256) {
            const int j = i >> 6, e = i & 63;
            Ks[e * SPAD + j] = Kt[i];
        }
        for (int i = tid * 4; i < 64 * 64; i += 256 * 4)
            *(float4*)&Vs[i] = *(const float4*)&Vt[i];
        __syncthreads();

        float s[4][4];
#pragma unroll
        for (int i = 0; i < 4; i++)
#pragma unroll
            for (int j = 0; j < 4; j++) s[i][j] = 0.0f;
#pragma unroll 8
        for (int e = 0; e < 64; e++) {
            const float4 q  = *(const float4*)&Qs[e * SPAD + tx * 4];
            const float4 kv = *(const float4*)&Ks[e * SPAD + ty * 4];
            const float qa[4] = {q.x, q.y, q.z, q.w};
            const float ka[4] = {kv.x, kv.y, kv.z, kv.w};
#pragma unroll
            for (int i = 0; i < 4; i++)
#pragma unroll
                for (int j = 0; j < 4; j++)
                    s[i][j] += qa[i] * ka[j];
        }
#pragma unroll
        for (int jj = 0; jj < 4; jj++) {
            const float mf = mflag[koff + ty * 4 + jj];
            float4 v;
            v.x = (mf != 0.0f) ? NEGBIG : s[0][jj];
            v.y = (mf != 0.0f) ? NEGBIG : s[1][jj];
            v.z = (mf != 0.0f) ? NEGBIG : s[2][jj];
            v.w = (mf != 0.0f) ? NEGBIG : s[3][jj];
            *(float4*)&Ss[(ty * 4 + jj) * SPAD + tx * 4] = v;
        }
        __syncthreads();

        if (tid < 64) {
            const float mold = m_s[tid];
            float mx = mold;
            for (int j = 0; j < 64; j++) mx = fmaxf(mx, Ss[j * SPAD + tid]);
            const float c = __expf(mold - mx);
            float sum = 0.0f;
            for (int j = 0; j < 64; j++) {
                const float p = __expf(Ss[j * SPAD + tid] - mx);
                Ss[j * SPAD + tid] = p;
                sum += p;
            }
            l_s[tid] = l_s[tid] * c + sum;
            m_s[tid] = mx;
            corr[tid] = c;
        }
        __syncthreads();

        const float c0 = corr[tx * 4 + 0];
        const float c1 = corr[tx * 4 + 1];
        const float c2 = corr[tx * 4 + 2];
        const float c3 = corr[tx * 4 + 3];
#pragma unroll
        for (int j = 0; j < 4; j++) {
            acc[0][j] *= c0; acc[1][j] *= c1; acc[2][j] *= c2; acc[3][j] *= c3;
        }
#pragma unroll 8
        for (int kk = 0; kk < 64; kk++) {
            const float4 p = *(const float4*)&Ss[kk * SPAD + tx * 4];
            const float4 v = *(const float4*)&Vs[kk * 64 + ty * 4];
            const float pa[4] = {p.x, p.y, p.z, p.w};
            const float va[4] = {v.x, v.y, v.z, v.w};
#pragma unroll
            for (int i = 0; i < 4; i++)
#pragma unroll
                for (int j = 0; j < 4; j++)
                    acc[i][j] += pa[i] * va[j];
        }
    }

    __syncthreads();
#pragma unroll
    for (int ii = 0; ii < 4; ii++) {
        const int r = tx * 4 + ii;
        const float inv = 1.0f / l_s[r];
        const int row = qt * 64 + r;
        const size_t base = ((size_t)b * Tq + row) * Dd + h * 64 + ty * 4;
        __align__(8) __nv_bfloat16 hv[4], lv[4];
#pragma unroll
        for (int j = 0; j < 4; j++) {
            const float v = acc[ii][j] * inv;
            hv[j] = __float2bfloat16(v);
            lv[j] = __float2bfloat16(v - __bfloat162float(hv[j]));
        }
        *(uint2*)&outh[base] = *(uint2*)hv;
        *(uint2*)&outl[base] = *(uint2*)lv;
    }
}

// ======================= launch =============================================
extern "C" void kernel_launch(void* const* d_in, const int* in_sizes, int n_in,
                              void* d_out, int out_size)
{
    const float* feats = (const float*)d_in[0];
    const float* inps  = (const float*)d_in[1];
    const int*   mask  = (const int*)d_in[2];
    const float* W_f  = (const float*)d_in[3];
    const float* b_f  = (const float*)d_in[4];
    const float* W_i  = (const float*)d_in[5];
    const float* b_i  = (const float*)d_in[6];
    const float* Wu_v = (const float*)d_in[7];
    const float* bu_v = (const float*)d_in[8];
    const float* Wu_l = (const float*)d_in[9];
    const float* bu_l = (const float*)d_in[10];
    float* out = (float*)d_out;

    float *pf, *pi;
    cudaGetSymbolAddress((void**)&pf, g_proj_f);
    cudaGetSymbolAddress((void**)&pi, g_proj_i);
    __nv_bfloat16 *fh, *fl, *ih, *il, *wfh, *wfl, *wih, *wil;
    __nv_bfloat16 *wuvh, *wuvl, *wulh, *wull, *avh, *avl, *alh, *all_;
    cudaGetSymbolAddress((void**)&fh, g_fh);   cudaGetSymbolAddress((void**)&fl, g_fl);
    cudaGetSymbolAddress((void**)&ih, g_ih);   cudaGetSymbolAddress((void**)&il, g_il);
    cudaGetSymbolAddress((void**)&wfh, g_wfh); cudaGetSymbolAddress((void**)&wfl, g_wfl);
    cudaGetSymbolAddress((void**)&wih, g_wih); cudaGetSymbolAddress((void**)&wil, g_wil);
    cudaGetSymbolAddress((void**)&wuvh, g_wuvh); cudaGetSymbolAddress((void**)&wuvl, g_wuvl);
    cudaGetSymbolAddress((void**)&wulh, g_wulh); cudaGetSymbolAddress((void**)&wull, g_wull);
    cudaGetSymbolAddress((void**)&avh, g_avh); cudaGetSymbolAddress((void**)&avl, g_avl);
    cudaGetSymbolAddress((void**)&alh, g_alh); cudaGetSymbolAddress((void**)&all_, g_all);

    const size_t SF = (size_t)Bb * T1c * Dd;  // 6291456
    const size_t SI = (size_t)Bb * T2c * Dd;  // 786432
    const int NF = (int)SF, NI = (int)SI;

    cudaFuncSetAttribute(gemm_mma, cudaFuncAttributeMaxDynamicSharedMemorySize, GEMM_SMEM);
    const int fsm = (3 * 64 * SPAD + 64 * 64 + 3 * 64 + (T1c + T2c)) * (int)sizeof(float);
    cudaFuncSetAttribute(flash_kernel, cudaFuncAttributeMaxDynamicSharedMemorySize, fsm);

    // Launches 1-5: conversions (exactly five, so ncu's "-s 5 -c 1" captures
    // launch #6 = the dominant projection gemm_mma).
    conv_split<<<(NF + 255) / 256, 256>>>(feats, fh, fl, NF);                 // 1
    conv_split<<<(NI + 255) / 256, 256>>>(inps, ih, il, NI);                  // 2
    conv_wsplit<<<dim3(24, 24, 6), 256>>>(W_f, wfh, wfl);                     // 3
    conv_wsplit<<<dim3(24, 24, 6), 256>>>(W_i, wih, wil);                     // 4
    conv_wsplit2<<<dim3(24, 24, 2), 256>>>(Wu_v, wuvh, wuvl, Wu_l, wulh, wull); // 5

    // 6: big projection GEMM (profiled next round)
    gemm_mma<<<dim3(6, 64, 6), 256, GEMM_SMEM>>>(fh, fl, wfh, wfl, b_f, pf,
                                                 Bb * T1c, T1c, PROJ_SCALE, 0);
    gemm_mma<<<dim3(6, 8, 6), 256, GEMM_SMEM>>>(ih, il, wih, wil, b_i, pi,
                                                Bb * T2c, T2c, PROJ_SCALE, 0);

    // attention (writes bf16 hi/lo directly — conv_split launches eliminated)
    flash_kernel<<<dim3(8, Hh, Bb), 256, fsm>>>(
        pf + 1 * SF, pf + 3 * SF, pf + 0 * SF, pf + 2 * SF,
        pi + 0 * SI, pi + 1 * SI, mask, avh, avl, T1c);
    flash_kernel<<<dim3(1, Hh, Bb), 256, fsm>>>(
        pi + 2 * SI, pi + 3 * SI, pf + 4 * SF, pf + 5 * SF,
        pi + 4 * SI, pi + 5 * SI, mask, alh, all_, T2c);

    // output projections
    gemm_mma<<<dim3(6, 64, 1), 256, GEMM_SMEM>>>(avh, avl, wuvh, wuvl, bu_v, out,
                                                 Bb * T1c, T1c, 1.0f, 1);
    gemm_mma<<<dim3(6, 8, 1), 256, GEMM_SMEM>>>(alh, all_, wulh, wull, bu_l, out + SF,
                                                Bb * T2c, T2c, 1.0f, 1);
}